// round 1
// baseline (speedup 1.0000x reference)
#include <cuda_runtime.h>
#include <stdint.h>

#define NVERT 100000
#define NEDGE 20000
#define NPAIR 1600000
#define FD 128
#define HDIM 128
#define ECAP 192
#define VCAP 64
#define BN_EPS 1e-5f

// ---------------- scratch (static __device__: no allocations allowed) --------
__device__ __align__(16) float g_h[(size_t)NVERT * HDIM];      // 51.2 MB
__device__ __align__(16) float g_Xe[(size_t)NEDGE * HDIM];     // 10.2 MB
__device__ int   g_ecnt[NEDGE];
__device__ int   g_vcnt[NVERT];
__device__ int   g_ebucket[(size_t)NEDGE * ECAP];              // 15.4 MB
__device__ int   g_vbucket[(size_t)NVERT * VCAP];              // 25.6 MB
__device__ float g_colsum[HDIM];
__device__ float g_colsumsq[HDIM];
__device__ float g_scale[HDIM];
__device__ float g_shift[HDIM];

// ---------------- bucket build: count + place in one pass --------------------
__global__ void fill_kernel(const int* __restrict__ vid, const int* __restrict__ eid) {
    int i = blockIdx.x * blockDim.x + threadIdx.x;
    if (i >= NPAIR) return;
    int v = vid[i];
    int e = eid[i];
    int a = atomicAdd(&g_ecnt[e], 1);
    if (a < ECAP) g_ebucket[(size_t)e * ECAP + a] = v;
    int c = atomicAdd(&g_vcnt[v], 1);
    if (c < VCAP) g_vbucket[(size_t)v * VCAP + c] = e;
}

// ---------------- SGEMM: h = X @ W + b  (128x128 tile, 8x8 micro) ------------
__global__ void gemm_kernel(const float* __restrict__ X, const float* __restrict__ W,
                            const float* __restrict__ bias) {
    __shared__ float As[16][132];   // transposed X tile: As[k][row]
    __shared__ float Bs[16][128];   // W tile: Bs[k][col]

    const int m0 = blockIdx.x * 128;
    const int tx = threadIdx.x & 15;
    const int ty = threadIdx.x >> 4;

    float acc[8][8];
#pragma unroll
    for (int i = 0; i < 8; i++)
#pragma unroll
        for (int j = 0; j < 8; j++) acc[i][j] = 0.f;

    const int lr = threadIdx.x >> 2;   // 0..63
    const int cg = threadIdx.x & 3;    // col group (4 floats)

    for (int k0 = 0; k0 < FD; k0 += 16) {
        // load X tile (128 rows x 16 cols), transpose into As
#pragma unroll
        for (int rr = 0; rr < 2; rr++) {
            int row = m0 + lr + rr * 64;
            float4 v = make_float4(0.f, 0.f, 0.f, 0.f);
            if (row < NVERT)
                v = *(const float4*)&X[(size_t)row * FD + k0 + cg * 4];
            As[cg * 4 + 0][lr + rr * 64] = v.x;
            As[cg * 4 + 1][lr + rr * 64] = v.y;
            As[cg * 4 + 2][lr + rr * 64] = v.z;
            As[cg * 4 + 3][lr + rr * 64] = v.w;
        }
        // load W tile (16 x 128)
#pragma unroll
        for (int q = 0; q < 2; q++) {
            int e  = threadIdx.x + q * 256;      // float4 index 0..511
            int kk = e >> 5;
            int cc = (e & 31) * 4;
            *(float4*)&Bs[kk][cc] = *(const float4*)&W[(size_t)(k0 + kk) * HDIM + cc];
        }
        __syncthreads();

#pragma unroll
        for (int kk = 0; kk < 16; kk++) {
            float4 a0 = *(const float4*)&As[kk][ty * 8];
            float4 a1 = *(const float4*)&As[kk][ty * 8 + 4];
            float4 b0 = *(const float4*)&Bs[kk][tx * 8];
            float4 b1 = *(const float4*)&Bs[kk][tx * 8 + 4];
            float a[8] = {a0.x, a0.y, a0.z, a0.w, a1.x, a1.y, a1.z, a1.w};
            float b[8] = {b0.x, b0.y, b0.z, b0.w, b1.x, b1.y, b1.z, b1.w};
#pragma unroll
            for (int i = 0; i < 8; i++)
#pragma unroll
                for (int j = 0; j < 8; j++) acc[i][j] += a[i] * b[j];
        }
        __syncthreads();
    }

    // epilogue: add bias, store h
    float bb[8];
#pragma unroll
    for (int j = 0; j < 8; j++) bb[j] = bias[tx * 8 + j];
#pragma unroll
    for (int i = 0; i < 8; i++) {
        int row = m0 + ty * 8 + i;
        if (row < NVERT) {
            float4 o0 = make_float4(acc[i][0] + bb[0], acc[i][1] + bb[1],
                                    acc[i][2] + bb[2], acc[i][3] + bb[3]);
            float4 o1 = make_float4(acc[i][4] + bb[4], acc[i][5] + bb[5],
                                    acc[i][6] + bb[6], acc[i][7] + bb[7]);
            *(float4*)&g_h[(size_t)row * HDIM + tx * 8]     = o0;
            *(float4*)&g_h[(size_t)row * HDIM + tx * 8 + 4] = o1;
        }
    }
}

// ---------------- column stats (sum, sumsq) over h ---------------------------
__global__ void stats_kernel() {
    const int c = threadIdx.x;        // 128 threads = one per column
    float s = 0.f, sq = 0.f;
#pragma unroll 4
    for (int r = blockIdx.x; r < NVERT; r += gridDim.x) {
        float v = g_h[(size_t)r * HDIM + c];
        s  += v;
        sq += v * v;
    }
    atomicAdd(&g_colsum[c], s);
    atomicAdd(&g_colsumsq[c], sq);
}

__global__ void finalize_stats(const float* __restrict__ gamma,
                               const float* __restrict__ beta) {
    int c = threadIdx.x;
    float mu  = g_colsum[c] * (1.0f / NVERT);
    float var = g_colsumsq[c] * (1.0f / NVERT) - mu * mu;
    float sc  = gamma[c] * rsqrtf(var + BN_EPS);
    g_scale[c] = sc;
    g_shift[c] = beta[c] - mu * sc;
}

// ---------------- phase 1: edge means (one warp per edge) --------------------
__global__ void edge_agg_kernel() {
    int w    = (blockIdx.x * blockDim.x + threadIdx.x) >> 5;
    int lane = threadIdx.x & 31;
    if (w >= NEDGE) return;

    int cnt   = g_ecnt[w];
    int n     = min(cnt, ECAP);
    const int* __restrict__ bucket = &g_ebucket[(size_t)w * ECAP];
    const float4* __restrict__ h4  = (const float4*)g_h;

    float4 acc = make_float4(0.f, 0.f, 0.f, 0.f);
    for (int j0 = 0; j0 < n; j0 += 32) {
        int my = (j0 + lane < n) ? bucket[j0 + lane] : 0;
        int nthis = min(32, n - j0);
#pragma unroll 4
        for (int t = 0; t < nthis; t++) {
            int v = __shfl_sync(0xffffffffu, my, t);
            float4 hv = __ldg(&h4[(size_t)v * 32 + lane]);
            acc.x += hv.x; acc.y += hv.y; acc.z += hv.z; acc.w += hv.w;
        }
    }

    float4 o = make_float4(0.f, 0.f, 0.f, 0.f);
    if (cnt > 0) {
        float inv = 1.0f / (float)cnt;
        float4 sc = ((const float4*)g_scale)[lane];
        float4 sh = ((const float4*)g_shift)[lane];
        o.x = fmaf(acc.x * inv, sc.x, sh.x);
        o.y = fmaf(acc.y * inv, sc.y, sh.y);
        o.z = fmaf(acc.z * inv, sc.z, sh.z);
        o.w = fmaf(acc.w * inv, sc.w, sh.w);
    }
    ((float4*)g_Xe)[(size_t)w * 32 + lane] = o;
}

// ---------------- phase 2: vertex means + ReLU (one warp per vertex) ---------
__global__ void vert_agg_kernel(float* __restrict__ out) {
    int w    = (blockIdx.x * blockDim.x + threadIdx.x) >> 5;
    int lane = threadIdx.x & 31;
    if (w >= NVERT) return;

    int cnt  = g_vcnt[w];
    int n    = min(cnt, VCAP);
    const int* __restrict__ bucket = &g_vbucket[(size_t)w * VCAP];
    const float4* __restrict__ xe4 = (const float4*)g_Xe;

    float4 acc = make_float4(0.f, 0.f, 0.f, 0.f);
    for (int j0 = 0; j0 < n; j0 += 32) {
        int my = (j0 + lane < n) ? bucket[j0 + lane] : 0;
        int nthis = min(32, n - j0);
#pragma unroll 4
        for (int t = 0; t < nthis; t++) {
            int e = __shfl_sync(0xffffffffu, my, t);
            float4 xv = __ldg(&xe4[(size_t)e * 32 + lane]);
            acc.x += xv.x; acc.y += xv.y; acc.z += xv.z; acc.w += xv.w;
        }
    }

    float inv = (cnt > 0) ? 1.0f / (float)cnt : 0.0f;
    float4 o;
    o.x = fmaxf(acc.x * inv, 0.f);
    o.y = fmaxf(acc.y * inv, 0.f);
    o.z = fmaxf(acc.z * inv, 0.f);
    o.w = fmaxf(acc.w * inv, 0.f);
    ((float4*)out)[(size_t)w * 32 + lane] = o;
}

// ---------------- launcher ---------------------------------------------------
extern "C" void kernel_launch(void* const* d_in, const int* in_sizes, int n_in,
                              void* d_out, int out_size) {
    const float* X     = (const float*)d_in[0];
    const int*   vid   = (const int*)d_in[1];
    const int*   eid   = (const int*)d_in[2];
    const float* W     = (const float*)d_in[3];
    const float* bias  = (const float*)d_in[4];
    const float* gamma = (const float*)d_in[5];
    const float* beta  = (const float*)d_in[6];
    float*       out   = (float*)d_out;

    void *p_ecnt, *p_vcnt, *p_cs, *p_cq;
    cudaGetSymbolAddress(&p_ecnt, g_ecnt);
    cudaGetSymbolAddress(&p_vcnt, g_vcnt);
    cudaGetSymbolAddress(&p_cs,   g_colsum);
    cudaGetSymbolAddress(&p_cq,   g_colsumsq);

    cudaMemsetAsync(p_ecnt, 0, NEDGE * sizeof(int));
    cudaMemsetAsync(p_vcnt, 0, NVERT * sizeof(int));
    cudaMemsetAsync(p_cs,   0, HDIM * sizeof(float));
    cudaMemsetAsync(p_cq,   0, HDIM * sizeof(float));

    fill_kernel<<<(NPAIR + 255) / 256, 256>>>(vid, eid);
    gemm_kernel<<<(NVERT + 127) / 128, 256>>>(X, W, bias);
    stats_kernel<<<1024, 128>>>();
    finalize_stats<<<1, 128>>>(gamma, beta);
    edge_agg_kernel<<<(NEDGE * 32 + 255) / 256, 256>>>();
    vert_agg_kernel<<<(NVERT * 32 + 255) / 256, 256>>>(out);
}

// round 2
// speedup vs baseline: 1.3091x; 1.3091x over previous
#include <cuda_runtime.h>
#include <cuda_fp16.h>
#include <stdint.h>

#define NVERT 100000
#define NEDGE 20000
#define NPAIR 1600000
#define FD 128
#define HDIM 128
#define ECAP 192
#define VCAP 64
#define BN_EPS 1e-5f

// ---------------- scratch (static __device__: no allocations allowed) --------
__device__ __align__(16) __half g_h[(size_t)NVERT * HDIM];     // 25.6 MB (fp16)
__device__ __align__(16) __half g_Xe[(size_t)NEDGE * HDIM];    // 5.1 MB (fp16)
__device__ int   g_ecnt[NEDGE];
__device__ int   g_vcnt[NVERT];
__device__ int   g_ebucket[(size_t)NEDGE * ECAP];              // 15.4 MB
__device__ int   g_vbucket[(size_t)NVERT * VCAP];              // 25.6 MB
__device__ float g_colsum[HDIM];
__device__ float g_colsumsq[HDIM];
__device__ float g_scale[HDIM];
__device__ float g_shift[HDIM];

// ---------------- bucket build: count + place in one pass --------------------
__global__ void fill_kernel(const int* __restrict__ vid, const int* __restrict__ eid) {
    int i = blockIdx.x * blockDim.x + threadIdx.x;
    if (i >= NPAIR) return;
    int v = vid[i];
    int e = eid[i];
    int a = atomicAdd(&g_ecnt[e], 1);
    if (a < ECAP) g_ebucket[(size_t)e * ECAP + a] = v;
    int c = atomicAdd(&g_vcnt[v], 1);
    if (c < VCAP) g_vbucket[(size_t)v * VCAP + c] = e;
}

// ---------------- SGEMM: h = X @ W + b, fused column stats -------------------
// 128x128 tile, 256 threads, 8x8 micro-tile. Stores h in fp16, accumulates
// per-column sum/sumsq in fp32 via smem reduction + one atomicAdd per column.
__global__ void gemm_kernel(const float* __restrict__ X, const float* __restrict__ W,
                            const float* __restrict__ bias) {
    __shared__ float As[16][132];    // transposed X tile: As[k][row]
    __shared__ float Bs[16][128];    // W tile: Bs[k][col]
    __shared__ float red[16][128];   // stats reduction buffer

    const int m0 = blockIdx.x * 128;
    const int tx = threadIdx.x & 15;
    const int ty = threadIdx.x >> 4;

    float acc[8][8];
#pragma unroll
    for (int i = 0; i < 8; i++)
#pragma unroll
        for (int j = 0; j < 8; j++) acc[i][j] = 0.f;

    const int lr = threadIdx.x >> 2;   // 0..63
    const int cg = threadIdx.x & 3;    // col group (4 floats)

    for (int k0 = 0; k0 < FD; k0 += 16) {
#pragma unroll
        for (int rr = 0; rr < 2; rr++) {
            int row = m0 + lr + rr * 64;
            float4 v = make_float4(0.f, 0.f, 0.f, 0.f);
            if (row < NVERT)
                v = *(const float4*)&X[(size_t)row * FD + k0 + cg * 4];
            As[cg * 4 + 0][lr + rr * 64] = v.x;
            As[cg * 4 + 1][lr + rr * 64] = v.y;
            As[cg * 4 + 2][lr + rr * 64] = v.z;
            As[cg * 4 + 3][lr + rr * 64] = v.w;
        }
#pragma unroll
        for (int q = 0; q < 2; q++) {
            int e  = threadIdx.x + q * 256;
            int kk = e >> 5;
            int cc = (e & 31) * 4;
            *(float4*)&Bs[kk][cc] = *(const float4*)&W[(size_t)(k0 + kk) * HDIM + cc];
        }
        __syncthreads();

#pragma unroll
        for (int kk = 0; kk < 16; kk++) {
            float4 a0 = *(const float4*)&As[kk][ty * 8];
            float4 a1 = *(const float4*)&As[kk][ty * 8 + 4];
            float4 b0 = *(const float4*)&Bs[kk][tx * 8];
            float4 b1 = *(const float4*)&Bs[kk][tx * 8 + 4];
            float a[8] = {a0.x, a0.y, a0.z, a0.w, a1.x, a1.y, a1.z, a1.w};
            float b[8] = {b0.x, b0.y, b0.z, b0.w, b1.x, b1.y, b1.z, b1.w};
#pragma unroll
            for (int i = 0; i < 8; i++)
#pragma unroll
                for (int j = 0; j < 8; j++) acc[i][j] += a[i] * b[j];
        }
        __syncthreads();
    }

    // epilogue: add bias, store h (fp16), accumulate col stats (fp32)
    float bb[8];
#pragma unroll
    for (int j = 0; j < 8; j++) bb[j] = bias[tx * 8 + j];

    float s[8], q[8];
#pragma unroll
    for (int j = 0; j < 8; j++) { s[j] = 0.f; q[j] = 0.f; }

#pragma unroll
    for (int i = 0; i < 8; i++) {
        int row = m0 + ty * 8 + i;
        if (row < NVERT) {
            float v[8];
#pragma unroll
            for (int j = 0; j < 8; j++) {
                v[j] = acc[i][j] + bb[j];
                s[j] += v[j];
                q[j] += v[j] * v[j];
            }
            // pack 8 floats -> 8 halves -> one 16B store
            __half2 h0 = __floats2half2_rn(v[0], v[1]);
            __half2 h1 = __floats2half2_rn(v[2], v[3]);
            __half2 h2 = __floats2half2_rn(v[4], v[5]);
            __half2 h3 = __floats2half2_rn(v[6], v[7]);
            uint4 pk;
            pk.x = *(uint32_t*)&h0; pk.y = *(uint32_t*)&h1;
            pk.z = *(uint32_t*)&h2; pk.w = *(uint32_t*)&h3;
            *(uint4*)&g_h[(size_t)row * HDIM + tx * 8] = pk;
        }
    }

    // column stats reduction
#pragma unroll
    for (int j = 0; j < 8; j++) red[ty][tx * 8 + j] = s[j];
    __syncthreads();
    if (threadIdx.x < 128) {
        float t = 0.f;
#pragma unroll
        for (int r = 0; r < 16; r++) t += red[r][threadIdx.x];
        atomicAdd(&g_colsum[threadIdx.x], t);
    }
    __syncthreads();
#pragma unroll
    for (int j = 0; j < 8; j++) red[ty][tx * 8 + j] = q[j];
    __syncthreads();
    if (threadIdx.x < 128) {
        float t = 0.f;
#pragma unroll
        for (int r = 0; r < 16; r++) t += red[r][threadIdx.x];
        atomicAdd(&g_colsumsq[threadIdx.x], t);
    }
}

__global__ void finalize_stats(const float* __restrict__ gamma,
                               const float* __restrict__ beta) {
    int c = threadIdx.x;
    float mu  = g_colsum[c] * (1.0f / NVERT);
    float var = g_colsumsq[c] * (1.0f / NVERT) - mu * mu;
    float sc  = gamma[c] * rsqrtf(var + BN_EPS);
    g_scale[c] = sc;
    g_shift[c] = beta[c] - mu * sc;
}

// ---------------- phase 1: edge means (one warp per edge, fp16 gather) -------
__global__ void edge_agg_kernel() {
    int w    = (blockIdx.x * blockDim.x + threadIdx.x) >> 5;
    int lane = threadIdx.x & 31;
    if (w >= NEDGE) return;

    int cnt = g_ecnt[w];
    int n   = min(cnt, ECAP);
    const int* __restrict__ bucket = &g_ebucket[(size_t)w * ECAP];
    const uint2* __restrict__ h2   = (const uint2*)g_h;  // 4 halves per uint2; 32 per row

    float acc0 = 0.f, acc1 = 0.f, acc2 = 0.f, acc3 = 0.f;
    for (int j0 = 0; j0 < n; j0 += 32) {
        int my = (j0 + lane < n) ? bucket[j0 + lane] : 0;
        int nthis = min(32, n - j0);
#pragma unroll 4
        for (int t = 0; t < nthis; t++) {
            int v = __shfl_sync(0xffffffffu, my, t);
            uint2 pk = __ldg(&h2[(size_t)v * 32 + lane]);
            float2 f0 = __half22float2(*(__half2*)&pk.x);
            float2 f1 = __half22float2(*(__half2*)&pk.y);
            acc0 += f0.x; acc1 += f0.y; acc2 += f1.x; acc3 += f1.y;
        }
    }

    uint2 opk; opk.x = 0u; opk.y = 0u;
    if (cnt > 0) {
        float inv = 1.0f / (float)cnt;
        float4 sc = ((const float4*)g_scale)[lane];
        float4 sh = ((const float4*)g_shift)[lane];
        float o0 = fmaf(acc0 * inv, sc.x, sh.x);
        float o1 = fmaf(acc1 * inv, sc.y, sh.y);
        float o2 = fmaf(acc2 * inv, sc.z, sh.z);
        float o3 = fmaf(acc3 * inv, sc.w, sh.w);
        __half2 p0 = __floats2half2_rn(o0, o1);
        __half2 p1 = __floats2half2_rn(o2, o3);
        opk.x = *(uint32_t*)&p0; opk.y = *(uint32_t*)&p1;
    }
    ((uint2*)g_Xe)[(size_t)w * 32 + lane] = opk;
}

// ---------------- phase 2: vertex means + ReLU (one warp per vertex) ---------
__global__ void vert_agg_kernel(float* __restrict__ out) {
    int w    = (blockIdx.x * blockDim.x + threadIdx.x) >> 5;
    int lane = threadIdx.x & 31;
    if (w >= NVERT) return;

    int cnt = g_vcnt[w];
    int n   = min(cnt, VCAP);
    const int* __restrict__ bucket = &g_vbucket[(size_t)w * VCAP];
    const uint2* __restrict__ xe2  = (const uint2*)g_Xe;

    float acc0 = 0.f, acc1 = 0.f, acc2 = 0.f, acc3 = 0.f;
    for (int j0 = 0; j0 < n; j0 += 32) {
        int my = (j0 + lane < n) ? bucket[j0 + lane] : 0;
        int nthis = min(32, n - j0);
#pragma unroll 4
        for (int t = 0; t < nthis; t++) {
            int e = __shfl_sync(0xffffffffu, my, t);
            uint2 pk = __ldg(&xe2[(size_t)e * 32 + lane]);
            float2 f0 = __half22float2(*(__half2*)&pk.x);
            float2 f1 = __half22float2(*(__half2*)&pk.y);
            acc0 += f0.x; acc1 += f0.y; acc2 += f1.x; acc3 += f1.y;
        }
    }

    float inv = (cnt > 0) ? 1.0f / (float)cnt : 0.0f;
    float4 o;
    o.x = fmaxf(acc0 * inv, 0.f);
    o.y = fmaxf(acc1 * inv, 0.f);
    o.z = fmaxf(acc2 * inv, 0.f);
    o.w = fmaxf(acc3 * inv, 0.f);
    ((float4*)out)[(size_t)w * 32 + lane] = o;
}

// ---------------- launcher ---------------------------------------------------
extern "C" void kernel_launch(void* const* d_in, const int* in_sizes, int n_in,
                              void* d_out, int out_size) {
    const float* X     = (const float*)d_in[0];
    const int*   vid   = (const int*)d_in[1];
    const int*   eid   = (const int*)d_in[2];
    const float* W     = (const float*)d_in[3];
    const float* bias  = (const float*)d_in[4];
    const float* gamma = (const float*)d_in[5];
    const float* beta  = (const float*)d_in[6];
    float*       out   = (float*)d_out;

    void *p_ecnt, *p_vcnt, *p_cs, *p_cq;
    cudaGetSymbolAddress(&p_ecnt, g_ecnt);
    cudaGetSymbolAddress(&p_vcnt, g_vcnt);
    cudaGetSymbolAddress(&p_cs,   g_colsum);
    cudaGetSymbolAddress(&p_cq,   g_colsumsq);

    cudaMemsetAsync(p_ecnt, 0, NEDGE * sizeof(int));
    cudaMemsetAsync(p_vcnt, 0, NVERT * sizeof(int));
    cudaMemsetAsync(p_cs,   0, HDIM * sizeof(float));
    cudaMemsetAsync(p_cq,   0, HDIM * sizeof(float));

    fill_kernel<<<(NPAIR + 255) / 256, 256>>>(vid, eid);
    gemm_kernel<<<(NVERT + 127) / 128, 256>>>(X, W, bias);
    finalize_stats<<<1, 128>>>(gamma, beta);
    edge_agg_kernel<<<(NEDGE * 32 + 255) / 256, 256>>>();
    vert_agg_kernel<<<(NVERT * 32 + 255) / 256, 256>>>(out);
}

// round 4
// speedup vs baseline: 1.6592x; 1.2674x over previous
#include <cuda_runtime.h>
#include <cuda_fp16.h>
#include <stdint.h>

#define NVERT 100000
#define NEDGE 20000
#define NPAIR 1600000
#define FD 128
#define HDIM 128
#define ECAP 192
#define VCAP 64
#define BN_EPS 1e-5f

// ---------------- scratch ----------------------------------------------------
__device__ __align__(16) __half g_h[(size_t)NVERT * HDIM];     // 25.6 MB (fp16)
__device__ __align__(16) __half g_Xe[(size_t)NEDGE * HDIM];    // 5.1 MB (fp16)
__device__ __align__(16) __half g_Wh[FD * HDIM];               // W^T in fp16 [n][k]
__device__ int   g_ecnt[NEDGE];
__device__ int   g_vcnt[NVERT];
__device__ int   g_ebucket[(size_t)NEDGE * ECAP];
__device__ int   g_vbucket[(size_t)NVERT * VCAP];
__device__ float g_colsum[HDIM];
__device__ float g_colsumsq[HDIM];
__device__ float g_scale[HDIM];
__device__ float g_shift[HDIM];

// ---------------- W transpose + fp16 convert (128 blocks x 128 thr) ----------
__global__ void wh_kernel(const float* __restrict__ W) {
    int n = blockIdx.x;       // output row (HMMA B is col-major = n-major)
    int k = threadIdx.x;
    g_Wh[n * FD + k] = __float2half(W[k * HDIM + n]);
}

// ---------------- bucket build -----------------------------------------------
__global__ void fill_kernel(const int* __restrict__ vid, const int* __restrict__ eid) {
    int i = blockIdx.x * blockDim.x + threadIdx.x;
    if (i >= NPAIR) return;
    int v = vid[i];
    int e = eid[i];
    int a = atomicAdd(&g_ecnt[e], 1);
    if (a < ECAP) g_ebucket[(size_t)e * ECAP + a] = v;
    int c = atomicAdd(&g_vcnt[v], 1);
    if (c < VCAP) g_vbucket[(size_t)v * VCAP + c] = e;
}

// ---------------- fp16 HMMA GEMM + bias + fp16 store + fused stats -----------
// block: 128 rows x 128 cols, 256 threads (8 warps, warp w -> rows w*16..w*16+15)
#define LDH 136                       // padded halves per row
#define SM_XS   0                     // 128*136*2 = 34816
#define SM_WS   34816                 // 34816
#define SM_SS   69632                 // float[8][128] = 4096
#define SM_SQ   73728                 // 4096
#define SM_BIAS 77824                 // 512
#define SM_TOTAL 78336

__global__ void __launch_bounds__(256) gemm_mma_kernel(const float* __restrict__ X,
                                                       const float* __restrict__ bias) {
    extern __shared__ char smem[];
    __half* Xs  = (__half*)(smem + SM_XS);
    __half* Ws  = (__half*)(smem + SM_WS);
    float*  ss  = (float*)(smem + SM_SS);
    float*  sq  = (float*)(smem + SM_SQ);
    float*  bsm = (float*)(smem + SM_BIAS);

    const int tid  = threadIdx.x;
    const int wid  = tid >> 5;
    const int lane = tid & 31;
    const int m0   = blockIdx.x * 128;

    if (tid < 32) ((float4*)bsm)[tid] = ((const float4*)bias)[tid];

    // W fp16 [n][k] -> smem (padded)
    {
        const __half2* __restrict__ Wh2 = (const __half2*)g_Wh;
#pragma unroll
        for (int i = 0; i < 32; i++) {
            int idx = tid + i * 256;          // 8192 half2
            int n = idx >> 6, k2 = idx & 63;
            *(__half2*)&Ws[n * LDH + k2 * 2] = Wh2[idx];
        }
    }
    // X tile fp32 -> fp16 smem (padded)
    {
        const float4* __restrict__ X4 = (const float4*)X;
#pragma unroll
        for (int i = 0; i < 16; i++) {
            int idx = tid + i * 256;          // 4096 float4
            int row = idx >> 5, c4 = idx & 31;
            int gr = m0 + row;
            float4 v = make_float4(0.f, 0.f, 0.f, 0.f);
            if (gr < NVERT) v = X4[(size_t)gr * 32 + c4];
            __half2 p0 = __floats2half2_rn(v.x, v.y);
            __half2 p1 = __floats2half2_rn(v.z, v.w);
            uint2 pk;
            pk.x = *(uint32_t*)&p0; pk.y = *(uint32_t*)&p1;
            *(uint2*)&Xs[row * LDH + c4 * 4] = pk;
        }
    }
    __syncthreads();

    const int g   = lane >> 2;   // 0..7
    const int tig = lane & 3;    // 0..3

    float d[16][4];
#pragma unroll
    for (int t = 0; t < 16; t++)
#pragma unroll
        for (int j = 0; j < 4; j++) d[t][j] = 0.f;

    const __half* Xw = Xs + (wid * 16) * LDH;
#pragma unroll
    for (int kk = 0; kk < 8; kk++) {
        const int kb = kk * 16 + tig * 2;
        uint32_t a0 = *(const uint32_t*)&Xw[g * LDH + kb];
        uint32_t a1 = *(const uint32_t*)&Xw[(g + 8) * LDH + kb];
        uint32_t a2 = *(const uint32_t*)&Xw[g * LDH + kb + 8];
        uint32_t a3 = *(const uint32_t*)&Xw[(g + 8) * LDH + kb + 8];
#pragma unroll
        for (int t = 0; t < 16; t++) {
            uint32_t b0 = *(const uint32_t*)&Ws[(t * 8 + g) * LDH + kb];
            uint32_t b1 = *(const uint32_t*)&Ws[(t * 8 + g) * LDH + kb + 8];
            asm volatile(
                "mma.sync.aligned.m16n8k16.row.col.f32.f16.f16.f32 "
                "{%0,%1,%2,%3},{%4,%5,%6,%7},{%8,%9},{%0,%1,%2,%3};"
                : "+f"(d[t][0]), "+f"(d[t][1]), "+f"(d[t][2]), "+f"(d[t][3])
                : "r"(a0), "r"(a1), "r"(a2), "r"(a3), "r"(b0), "r"(b1));
        }
    }

    // epilogue: bias, fp16 store, fused column stats
    const int row0 = wid * 16 + g;
    const int gr0  = m0 + row0;
    const int gr1  = gr0 + 8;
    const bool ok0 = gr0 < NVERT;
    const bool ok1 = gr1 < NVERT;

#pragma unroll
    for (int t = 0; t < 16; t++) {
        const int c = t * 8 + tig * 2;
        float b0f = bsm[c], b1f = bsm[c + 1];
        float v0 = d[t][0] + b0f, v1 = d[t][1] + b1f;
        float v2 = d[t][2] + b0f, v3 = d[t][3] + b1f;
        if (ok0) *(__half2*)&g_h[(size_t)gr0 * HDIM + c] = __floats2half2_rn(v0, v1);
        if (ok1) *(__half2*)&g_h[(size_t)gr1 * HDIM + c] = __floats2half2_rn(v2, v3);

        float s0 = (ok0 ? v0 : 0.f) + (ok1 ? v2 : 0.f);
        float s1 = (ok0 ? v1 : 0.f) + (ok1 ? v3 : 0.f);
        float q0 = (ok0 ? v0 * v0 : 0.f) + (ok1 ? v2 * v2 : 0.f);
        float q1 = (ok0 ? v1 * v1 : 0.f) + (ok1 ? v3 * v3 : 0.f);
#pragma unroll
        for (int m = 4; m <= 16; m <<= 1) {
            s0 += __shfl_xor_sync(0xffffffffu, s0, m);
            s1 += __shfl_xor_sync(0xffffffffu, s1, m);
            q0 += __shfl_xor_sync(0xffffffffu, q0, m);
            q1 += __shfl_xor_sync(0xffffffffu, q1, m);
        }
        if (g == 0) {
            ss[wid * 128 + c] = s0; ss[wid * 128 + c + 1] = s1;
            sq[wid * 128 + c] = q0; sq[wid * 128 + c + 1] = q1;
        }
    }
    __syncthreads();

    if (tid < 128) {
        float t = 0.f;
#pragma unroll
        for (int r = 0; r < 8; r++) t += ss[r * 128 + tid];
        atomicAdd(&g_colsum[tid], t);
    } else {
        int c = tid - 128;
        float t = 0.f;
#pragma unroll
        for (int r = 0; r < 8; r++) t += sq[r * 128 + c];
        atomicAdd(&g_colsumsq[c], t);
    }
}

__global__ void finalize_stats(const float* __restrict__ gamma,
                               const float* __restrict__ beta) {
    int c = threadIdx.x;
    float mu  = g_colsum[c] * (1.0f / NVERT);
    float var = g_colsumsq[c] * (1.0f / NVERT) - mu * mu;
    float sc  = gamma[c] * rsqrtf(var + BN_EPS);
    g_scale[c] = sc;
    g_shift[c] = beta[c] - mu * sc;
}

// ---------------- phase 1: edge means (one warp per edge, fp16 gather) -------
__global__ void edge_agg_kernel() {
    int w    = (blockIdx.x * blockDim.x + threadIdx.x) >> 5;
    int lane = threadIdx.x & 31;
    if (w >= NEDGE) return;

    int cnt = g_ecnt[w];
    int n   = min(cnt, ECAP);
    const int* __restrict__ bucket = &g_ebucket[(size_t)w * ECAP];
    const uint2* __restrict__ h2   = (const uint2*)g_h;

    float acc0 = 0.f, acc1 = 0.f, acc2 = 0.f, acc3 = 0.f;
    for (int j0 = 0; j0 < n; j0 += 32) {
        int my = (j0 + lane < n) ? bucket[j0 + lane] : 0;
        int nthis = min(32, n - j0);
#pragma unroll 4
        for (int t = 0; t < nthis; t++) {
            int v = __shfl_sync(0xffffffffu, my, t);
            uint2 pk = __ldg(&h2[(size_t)v * 32 + lane]);
            float2 f0 = __half22float2(*(__half2*)&pk.x);
            float2 f1 = __half22float2(*(__half2*)&pk.y);
            acc0 += f0.x; acc1 += f0.y; acc2 += f1.x; acc3 += f1.y;
        }
    }

    uint2 opk; opk.x = 0u; opk.y = 0u;
    if (cnt > 0) {
        float inv = 1.0f / (float)cnt;
        float4 sc = ((const float4*)g_scale)[lane];
        float4 sh = ((const float4*)g_shift)[lane];
        float o0 = fmaf(acc0 * inv, sc.x, sh.x);
        float o1 = fmaf(acc1 * inv, sc.y, sh.y);
        float o2 = fmaf(acc2 * inv, sc.z, sh.z);
        float o3 = fmaf(acc3 * inv, sc.w, sh.w);
        __half2 p0 = __floats2half2_rn(o0, o1);
        __half2 p1 = __floats2half2_rn(o2, o3);
        opk.x = *(uint32_t*)&p0; opk.y = *(uint32_t*)&p1;
    }
    ((uint2*)g_Xe)[(size_t)w * 32 + lane] = opk;
}

// ---------------- phase 2: vertex means + ReLU -------------------------------
__global__ void vert_agg_kernel(float* __restrict__ out) {
    int w    = (blockIdx.x * blockDim.x + threadIdx.x) >> 5;
    int lane = threadIdx.x & 31;
    if (w >= NVERT) return;

    int cnt = g_vcnt[w];
    int n   = min(cnt, VCAP);
    const int* __restrict__ bucket = &g_vbucket[(size_t)w * VCAP];
    const uint2* __restrict__ xe2  = (const uint2*)g_Xe;

    float acc0 = 0.f, acc1 = 0.f, acc2 = 0.f, acc3 = 0.f;
    for (int j0 = 0; j0 < n; j0 += 32) {
        int my = (j0 + lane < n) ? bucket[j0 + lane] : 0;
        int nthis = min(32, n - j0);
#pragma unroll 4
        for (int t = 0; t < nthis; t++) {
            int e = __shfl_sync(0xffffffffu, my, t);
            uint2 pk = __ldg(&xe2[(size_t)e * 32 + lane]);
            float2 f0 = __half22float2(*(__half2*)&pk.x);
            float2 f1 = __half22float2(*(__half2*)&pk.y);
            acc0 += f0.x; acc1 += f0.y; acc2 += f1.x; acc3 += f1.y;
        }
    }

    float inv = (cnt > 0) ? 1.0f / (float)cnt : 0.0f;
    float4 o;
    o.x = fmaxf(acc0 * inv, 0.f);
    o.y = fmaxf(acc1 * inv, 0.f);
    o.z = fmaxf(acc2 * inv, 0.f);
    o.w = fmaxf(acc3 * inv, 0.f);
    ((float4*)out)[(size_t)w * 32 + lane] = o;
}

// ---------------- launcher ---------------------------------------------------
extern "C" void kernel_launch(void* const* d_in, const int* in_sizes, int n_in,
                              void* d_out, int out_size) {
    const float* X     = (const float*)d_in[0];
    const int*   vid   = (const int*)d_in[1];
    const int*   eid   = (const int*)d_in[2];
    const float* W     = (const float*)d_in[3];
    const float* bias  = (const float*)d_in[4];
    const float* gamma = (const float*)d_in[5];
    const float* beta  = (const float*)d_in[6];
    float*       out   = (float*)d_out;

    cudaFuncSetAttribute(gemm_mma_kernel, cudaFuncAttributeMaxDynamicSharedMemorySize, SM_TOTAL);

    void *p_ecnt, *p_vcnt, *p_cs, *p_cq;
    cudaGetSymbolAddress(&p_ecnt, g_ecnt);
    cudaGetSymbolAddress(&p_vcnt, g_vcnt);
    cudaGetSymbolAddress(&p_cs,   g_colsum);
    cudaGetSymbolAddress(&p_cq,   g_colsumsq);

    cudaMemsetAsync(p_ecnt, 0, NEDGE * sizeof(int));
    cudaMemsetAsync(p_vcnt, 0, NVERT * sizeof(int));
    cudaMemsetAsync(p_cs,   0, HDIM * sizeof(float));
    cudaMemsetAsync(p_cq,   0, HDIM * sizeof(float));

    wh_kernel<<<128, 128>>>(W);
    fill_kernel<<<(NPAIR + 255) / 256, 256>>>(vid, eid);
    gemm_mma_kernel<<<(NVERT + 127) / 128, 256, SM_TOTAL>>>(X, bias);
    finalize_stats<<<1, 128>>>(gamma, beta);
    edge_agg_kernel<<<(NEDGE * 32 + 255) / 256, 256>>>();
    vert_agg_kernel<<<(NVERT * 32 + 255) / 256, 256>>>(out);
}

// round 5
// speedup vs baseline: 1.7164x; 1.0345x over previous
#include <cuda_runtime.h>
#include <cuda_fp16.h>
#include <stdint.h>

#define NVERT 100000
#define NEDGE 20000
#define NPAIR 1600000
#define FD 128
#define HDIM 128
#define ECAP 192
#define VCAP 64
#define BN_EPS 1e-5f

// ---------------- scratch ----------------------------------------------------
__device__ __align__(16) __half g_h[(size_t)NVERT * HDIM];     // 25.6 MB (fp16)
__device__ __align__(16) __half g_Xe[(size_t)NEDGE * HDIM];    // 5.1 MB (fp16)
__device__ __align__(16) __half g_Wh[FD * HDIM];               // W^T in fp16 [n][k]
__device__ int   g_ecnt[NEDGE];
__device__ int   g_vcnt[NVERT];
__device__ int   g_ebucket[(size_t)NEDGE * ECAP];
__device__ int   g_vbucket[(size_t)NVERT * VCAP];
__device__ float g_colsum[HDIM];
__device__ float g_colsumsq[HDIM];
__device__ float g_scale[HDIM];
__device__ float g_shift[HDIM];

// ---------------- W transpose + fp16 convert ---------------------------------
__global__ void wh_kernel(const float* __restrict__ W) {
    int n = blockIdx.x;
    int k = threadIdx.x;
    g_Wh[n * FD + k] = __float2half(W[k * HDIM + n]);
}

// ---------------- bucket build (4 pairs per thread) --------------------------
__global__ void fill_kernel(const int* __restrict__ vid, const int* __restrict__ eid) {
    int i = blockIdx.x * blockDim.x + threadIdx.x;
    if (i >= NPAIR / 4) return;
    int4 v4 = ((const int4*)vid)[i];
    int4 e4 = ((const int4*)eid)[i];
    int vv[4] = {v4.x, v4.y, v4.z, v4.w};
    int ee[4] = {e4.x, e4.y, e4.z, e4.w};
#pragma unroll
    for (int t = 0; t < 4; t++) {
        int a = atomicAdd(&g_ecnt[ee[t]], 1);
        if (a < ECAP) g_ebucket[(size_t)ee[t] * ECAP + a] = vv[t];
        int c = atomicAdd(&g_vcnt[vv[t]], 1);
        if (c < VCAP) g_vbucket[(size_t)vv[t] * VCAP + c] = ee[t];
    }
}

// ---------------- fp16 HMMA GEMM + bias + fp16 store + fused stats -----------
#define LDH 136
#define SM_XS   0
#define SM_WS   34816
#define SM_SS   69632
#define SM_SQ   73728
#define SM_BIAS 77824
#define SM_TOTAL 78336

__global__ void __launch_bounds__(256, 2) gemm_mma_kernel(const float* __restrict__ X,
                                                          const float* __restrict__ bias) {
    extern __shared__ char smem[];
    __half* Xs  = (__half*)(smem + SM_XS);
    __half* Ws  = (__half*)(smem + SM_WS);
    float*  ss  = (float*)(smem + SM_SS);
    float*  sq  = (float*)(smem + SM_SQ);
    float*  bsm = (float*)(smem + SM_BIAS);

    const int tid  = threadIdx.x;
    const int wid  = tid >> 5;
    const int lane = tid & 31;
    const int m0   = blockIdx.x * 128;

    if (tid < 32) ((float4*)bsm)[tid] = ((const float4*)bias)[tid];

    {
        const __half2* __restrict__ Wh2 = (const __half2*)g_Wh;
#pragma unroll
        for (int i = 0; i < 32; i++) {
            int idx = tid + i * 256;
            int n = idx >> 6, k2 = idx & 63;
            *(__half2*)&Ws[n * LDH + k2 * 2] = Wh2[idx];
        }
    }
    {
        const float4* __restrict__ X4 = (const float4*)X;
#pragma unroll
        for (int i = 0; i < 16; i++) {
            int idx = tid + i * 256;
            int row = idx >> 5, c4 = idx & 31;
            int gr = m0 + row;
            float4 v = make_float4(0.f, 0.f, 0.f, 0.f);
            if (gr < NVERT) v = X4[(size_t)gr * 32 + c4];
            __half2 p0 = __floats2half2_rn(v.x, v.y);
            __half2 p1 = __floats2half2_rn(v.z, v.w);
            uint2 pk;
            pk.x = *(uint32_t*)&p0; pk.y = *(uint32_t*)&p1;
            *(uint2*)&Xs[row * LDH + c4 * 4] = pk;
        }
    }
    __syncthreads();

    const int g   = lane >> 2;
    const int tig = lane & 3;

    float d[16][4];
#pragma unroll
    for (int t = 0; t < 16; t++)
#pragma unroll
        for (int j = 0; j < 4; j++) d[t][j] = 0.f;

    const __half* Xw = Xs + (wid * 16) * LDH;
#pragma unroll
    for (int kk = 0; kk < 8; kk++) {
        const int kb = kk * 16 + tig * 2;
        uint32_t a0 = *(const uint32_t*)&Xw[g * LDH + kb];
        uint32_t a1 = *(const uint32_t*)&Xw[(g + 8) * LDH + kb];
        uint32_t a2 = *(const uint32_t*)&Xw[g * LDH + kb + 8];
        uint32_t a3 = *(const uint32_t*)&Xw[(g + 8) * LDH + kb + 8];
#pragma unroll
        for (int t = 0; t < 16; t++) {
            uint32_t b0 = *(const uint32_t*)&Ws[(t * 8 + g) * LDH + kb];
            uint32_t b1 = *(const uint32_t*)&Ws[(t * 8 + g) * LDH + kb + 8];
            asm volatile(
                "mma.sync.aligned.m16n8k16.row.col.f32.f16.f16.f32 "
                "{%0,%1,%2,%3},{%4,%5,%6,%7},{%8,%9},{%0,%1,%2,%3};"
                : "+f"(d[t][0]), "+f"(d[t][1]), "+f"(d[t][2]), "+f"(d[t][3])
                : "r"(a0), "r"(a1), "r"(a2), "r"(a3), "r"(b0), "r"(b1));
        }
    }

    const int row0 = wid * 16 + g;
    const int gr0  = m0 + row0;
    const int gr1  = gr0 + 8;
    const bool ok0 = gr0 < NVERT;
    const bool ok1 = gr1 < NVERT;

#pragma unroll
    for (int t = 0; t < 16; t++) {
        const int c = t * 8 + tig * 2;
        float b0f = bsm[c], b1f = bsm[c + 1];
        float v0 = d[t][0] + b0f, v1 = d[t][1] + b1f;
        float v2 = d[t][2] + b0f, v3 = d[t][3] + b1f;
        if (ok0) *(__half2*)&g_h[(size_t)gr0 * HDIM + c] = __floats2half2_rn(v0, v1);
        if (ok1) *(__half2*)&g_h[(size_t)gr1 * HDIM + c] = __floats2half2_rn(v2, v3);

        float s0 = (ok0 ? v0 : 0.f) + (ok1 ? v2 : 0.f);
        float s1 = (ok0 ? v1 : 0.f) + (ok1 ? v3 : 0.f);
        float q0 = (ok0 ? v0 * v0 : 0.f) + (ok1 ? v2 * v2 : 0.f);
        float q1 = (ok0 ? v1 * v1 : 0.f) + (ok1 ? v3 * v3 : 0.f);
#pragma unroll
        for (int m = 4; m <= 16; m <<= 1) {
            s0 += __shfl_xor_sync(0xffffffffu, s0, m);
            s1 += __shfl_xor_sync(0xffffffffu, s1, m);
            q0 += __shfl_xor_sync(0xffffffffu, q0, m);
            q1 += __shfl_xor_sync(0xffffffffu, q1, m);
        }
        if (g == 0) {
            ss[wid * 128 + c] = s0; ss[wid * 128 + c + 1] = s1;
            sq[wid * 128 + c] = q0; sq[wid * 128 + c + 1] = q1;
        }
    }
    __syncthreads();

    if (tid < 128) {
        float t = 0.f;
#pragma unroll
        for (int r = 0; r < 8; r++) t += ss[r * 128 + tid];
        atomicAdd(&g_colsum[tid], t);
    } else {
        int c = tid - 128;
        float t = 0.f;
#pragma unroll
        for (int r = 0; r < 8; r++) t += sq[r * 128 + c];
        atomicAdd(&g_colsumsq[c], t);
    }
}

__global__ void finalize_stats(const float* __restrict__ gamma,
                               const float* __restrict__ beta) {
    int c = threadIdx.x;
    float mu  = g_colsum[c] * (1.0f / NVERT);
    float var = g_colsumsq[c] * (1.0f / NVERT) - mu * mu;
    float sc  = gamma[c] * rsqrtf(var + BN_EPS);
    g_scale[c] = sc;
    g_shift[c] = beta[c] - mu * sc;
}

// ---------------- phase 1: edge means ----------------------------------------
// warp per edge; 16 lanes x uint4 per row; two bucket entries per inner step
__global__ void edge_agg_kernel() {
    int w    = (blockIdx.x * blockDim.x + threadIdx.x) >> 5;
    int lane = threadIdx.x & 31;
    if (w >= NEDGE) return;

    int cnt = g_ecnt[w];
    int n   = min(cnt, ECAP);
    const int* __restrict__ bucket = &g_ebucket[(size_t)w * ECAP];
    const uint4* __restrict__ h4   = (const uint4*)g_h;   // 8 halves each; 16 per row

    const int half = lane >> 4;       // 0: even entries, 1: odd entries
    const int sub  = lane & 15;       // column group: cols sub*8 .. sub*8+7

    float a0 = 0.f, a1 = 0.f, a2 = 0.f, a3 = 0.f;
    float a4 = 0.f, a5 = 0.f, a6 = 0.f, a7 = 0.f;

    for (int j0 = 0; j0 < n; j0 += 32) {
        int my = (j0 + lane < n) ? bucket[j0 + lane] : 0;
        int nthis = min(32, n - j0);
#pragma unroll 2
        for (int t = 0; t < nthis; t += 2) {
            int idx = t + half;
            int v = __shfl_sync(0xffffffffu, my, idx);
            if (idx < nthis) {
                uint4 pk = __ldg(&h4[(size_t)v * 16 + sub]);
                float2 f0 = __half22float2(*(__half2*)&pk.x);
                float2 f1 = __half22float2(*(__half2*)&pk.y);
                float2 f2 = __half22float2(*(__half2*)&pk.z);
                float2 f3 = __half22float2(*(__half2*)&pk.w);
                a0 += f0.x; a1 += f0.y; a2 += f1.x; a3 += f1.y;
                a4 += f2.x; a5 += f2.y; a6 += f3.x; a7 += f3.y;
            }
        }
    }

    // combine odd-half partials into even half
    a0 += __shfl_down_sync(0xffffffffu, a0, 16);
    a1 += __shfl_down_sync(0xffffffffu, a1, 16);
    a2 += __shfl_down_sync(0xffffffffu, a2, 16);
    a3 += __shfl_down_sync(0xffffffffu, a3, 16);
    a4 += __shfl_down_sync(0xffffffffu, a4, 16);
    a5 += __shfl_down_sync(0xffffffffu, a5, 16);
    a6 += __shfl_down_sync(0xffffffffu, a6, 16);
    a7 += __shfl_down_sync(0xffffffffu, a7, 16);

    if (lane < 16) {
        uint4 opk; opk.x = opk.y = opk.z = opk.w = 0u;
        if (cnt > 0) {
            float inv = 1.0f / (float)cnt;
            float4 sc0 = ((const float4*)g_scale)[sub * 2];
            float4 sc1 = ((const float4*)g_scale)[sub * 2 + 1];
            float4 sh0 = ((const float4*)g_shift)[sub * 2];
            float4 sh1 = ((const float4*)g_shift)[sub * 2 + 1];
            __half2 p0 = __floats2half2_rn(fmaf(a0 * inv, sc0.x, sh0.x), fmaf(a1 * inv, sc0.y, sh0.y));
            __half2 p1 = __floats2half2_rn(fmaf(a2 * inv, sc0.z, sh0.z), fmaf(a3 * inv, sc0.w, sh0.w));
            __half2 p2 = __floats2half2_rn(fmaf(a4 * inv, sc1.x, sh1.x), fmaf(a5 * inv, sc1.y, sh1.y));
            __half2 p3 = __floats2half2_rn(fmaf(a6 * inv, sc1.z, sh1.z), fmaf(a7 * inv, sc1.w, sh1.w));
            opk.x = *(uint32_t*)&p0; opk.y = *(uint32_t*)&p1;
            opk.z = *(uint32_t*)&p2; opk.w = *(uint32_t*)&p3;
        }
        ((uint4*)g_Xe)[(size_t)w * 16 + sub] = opk;
    }
}

// ---------------- phase 2: vertex means + ReLU -------------------------------
__global__ void vert_agg_kernel(float* __restrict__ out) {
    int w    = (blockIdx.x * blockDim.x + threadIdx.x) >> 5;
    int lane = threadIdx.x & 31;
    if (w >= NVERT) return;

    int cnt = g_vcnt[w];
    int n   = min(cnt, VCAP);
    const int* __restrict__ bucket = &g_vbucket[(size_t)w * VCAP];
    const uint4* __restrict__ xe4  = (const uint4*)g_Xe;

    const int half = lane >> 4;
    const int sub  = lane & 15;

    float a0 = 0.f, a1 = 0.f, a2 = 0.f, a3 = 0.f;
    float a4 = 0.f, a5 = 0.f, a6 = 0.f, a7 = 0.f;

    for (int j0 = 0; j0 < n; j0 += 32) {
        int my = (j0 + lane < n) ? bucket[j0 + lane] : 0;
        int nthis = min(32, n - j0);
#pragma unroll 2
        for (int t = 0; t < nthis; t += 2) {
            int idx = t + half;
            int e = __shfl_sync(0xffffffffu, my, idx);
            if (idx < nthis) {
                uint4 pk = __ldg(&xe4[(size_t)e * 16 + sub]);
                float2 f0 = __half22float2(*(__half2*)&pk.x);
                float2 f1 = __half22float2(*(__half2*)&pk.y);
                float2 f2 = __half22float2(*(__half2*)&pk.z);
                float2 f3 = __half22float2(*(__half2*)&pk.w);
                a0 += f0.x; a1 += f0.y; a2 += f1.x; a3 += f1.y;
                a4 += f2.x; a5 += f2.y; a6 += f3.x; a7 += f3.y;
            }
        }
    }

    a0 += __shfl_down_sync(0xffffffffu, a0, 16);
    a1 += __shfl_down_sync(0xffffffffu, a1, 16);
    a2 += __shfl_down_sync(0xffffffffu, a2, 16);
    a3 += __shfl_down_sync(0xffffffffu, a3, 16);
    a4 += __shfl_down_sync(0xffffffffu, a4, 16);
    a5 += __shfl_down_sync(0xffffffffu, a5, 16);
    a6 += __shfl_down_sync(0xffffffffu, a6, 16);
    a7 += __shfl_down_sync(0xffffffffu, a7, 16);

    if (lane < 16) {
        float inv = (cnt > 0) ? 1.0f / (float)cnt : 0.0f;
        float4 o0, o1;
        o0.x = fmaxf(a0 * inv, 0.f); o0.y = fmaxf(a1 * inv, 0.f);
        o0.z = fmaxf(a2 * inv, 0.f); o0.w = fmaxf(a3 * inv, 0.f);
        o1.x = fmaxf(a4 * inv, 0.f); o1.y = fmaxf(a5 * inv, 0.f);
        o1.z = fmaxf(a6 * inv, 0.f); o1.w = fmaxf(a7 * inv, 0.f);
        ((float4*)out)[(size_t)w * 32 + sub * 2]     = o0;
        ((float4*)out)[(size_t)w * 32 + sub * 2 + 1] = o1;
    }
}

// ---------------- launcher: fork bucket-build onto side stream ---------------
extern "C" void kernel_launch(void* const* d_in, const int* in_sizes, int n_in,
                              void* d_out, int out_size) {
    const float* X     = (const float*)d_in[0];
    const int*   vid   = (const int*)d_in[1];
    const int*   eid   = (const int*)d_in[2];
    const float* W     = (const float*)d_in[3];
    const float* bias  = (const float*)d_in[4];
    const float* gamma = (const float*)d_in[5];
    const float* beta  = (const float*)d_in[6];
    float*       out   = (float*)d_out;

    static cudaStream_t sB = nullptr;
    static cudaEvent_t evFork = nullptr, evJoin = nullptr;
    if (sB == nullptr) {
        cudaStreamCreateWithFlags(&sB, cudaStreamNonBlocking);
        cudaEventCreateWithFlags(&evFork, cudaEventDisableTiming);
        cudaEventCreateWithFlags(&evJoin, cudaEventDisableTiming);
        cudaFuncSetAttribute(gemm_mma_kernel, cudaFuncAttributeMaxDynamicSharedMemorySize, SM_TOTAL);
    }

    void *p_ecnt, *p_vcnt, *p_cs, *p_cq;
    cudaGetSymbolAddress(&p_ecnt, g_ecnt);
    cudaGetSymbolAddress(&p_vcnt, g_vcnt);
    cudaGetSymbolAddress(&p_cs,   g_colsum);
    cudaGetSymbolAddress(&p_cq,   g_colsumsq);

    // fork side stream for the bucket build
    cudaEventRecord(evFork, 0);
    cudaStreamWaitEvent(sB, evFork, 0);
    cudaMemsetAsync(p_ecnt, 0, NEDGE * sizeof(int), sB);
    cudaMemsetAsync(p_vcnt, 0, NVERT * sizeof(int), sB);
    fill_kernel<<<(NPAIR / 4 + 255) / 256, 256, 0, sB>>>(vid, eid);
    cudaEventRecord(evJoin, sB);

    // main (capture) stream: GEMM chain
    cudaMemsetAsync(p_cs, 0, HDIM * sizeof(float));
    cudaMemsetAsync(p_cq, 0, HDIM * sizeof(float));
    wh_kernel<<<128, 128>>>(W);
    gemm_mma_kernel<<<(NVERT + 127) / 128, 256, SM_TOTAL>>>(X, bias);
    finalize_stats<<<1, 128>>>(gamma, beta);

    // join, then aggregation phases
    cudaStreamWaitEvent(0, evJoin, 0);
    edge_agg_kernel<<<(NEDGE * 32 + 255) / 256, 256>>>();
    vert_agg_kernel<<<(NVERT * 32 + 255) / 256, 256>>>(out);
}

// round 6
// speedup vs baseline: 1.7317x; 1.0089x over previous
#include <cuda_runtime.h>
#include <cuda_fp16.h>
#include <stdint.h>

#define NVERT 100000
#define NEDGE 20000
#define NPAIR 1600000
#define FD 128
#define HDIM 128
#define ECAP 192
#define VCAP 64
#define BN_EPS 1e-5f

// ---------------- scratch ----------------------------------------------------
__device__ __align__(16) __half g_h[(size_t)NVERT * HDIM];     // 25.6 MB (fp16)
__device__ __align__(16) __half g_Xe[(size_t)NEDGE * HDIM];    // 5.1 MB (fp16)
__device__ __align__(16) __half g_Wh[FD * HDIM];               // W^T in fp16 [n][k]
__device__ int   g_ecnt[NEDGE];
__device__ int   g_vcnt[NVERT];
__device__ int   g_ebucket[(size_t)NEDGE * ECAP];
__device__ int   g_vbucket[(size_t)NVERT * VCAP];
__device__ float g_colsum[HDIM];
__device__ float g_colsumsq[HDIM];

// ---------------- prep: W transpose->fp16 + zero stats (one kernel) ----------
__global__ void prep_kernel(const float* __restrict__ W) {
    int idx = blockIdx.x * 256 + threadIdx.x;     // 64 blocks x 256 = 16384
    int k = idx >> 7, n = idx & 127;
    g_Wh[n * FD + k] = __float2half(W[idx]);      // coalesced read W[k][n]
    if (blockIdx.x == 0 && threadIdx.x < 128) {
        g_colsum[threadIdx.x]   = 0.f;
        g_colsumsq[threadIdx.x] = 0.f;
    }
}

// ---------------- bucket build (4 pairs per thread) --------------------------
__global__ void fill_kernel(const int* __restrict__ vid, const int* __restrict__ eid) {
    int i = blockIdx.x * blockDim.x + threadIdx.x;
    if (i >= NPAIR / 4) return;
    int4 v4 = ((const int4*)vid)[i];
    int4 e4 = ((const int4*)eid)[i];
    int vv[4] = {v4.x, v4.y, v4.z, v4.w};
    int ee[4] = {e4.x, e4.y, e4.z, e4.w};
#pragma unroll
    for (int t = 0; t < 4; t++) {
        int a = atomicAdd(&g_ecnt[ee[t]], 1);
        if (a < ECAP) g_ebucket[(size_t)ee[t] * ECAP + a] = vv[t];
        int c = atomicAdd(&g_vcnt[vv[t]], 1);
        if (c < VCAP) g_vbucket[(size_t)vv[t] * VCAP + c] = ee[t];
    }
}

// ---------------- fp16 HMMA GEMM + bias + fp16 store + fused stats -----------
#define LDH 136
#define SM_XS   0
#define SM_WS   34816
#define SM_SS   69632
#define SM_SQ   73728
#define SM_BIAS 77824
#define SM_TOTAL 78336

__global__ void __launch_bounds__(256, 2) gemm_mma_kernel(const float* __restrict__ X,
                                                          const float* __restrict__ bias) {
    extern __shared__ char smem[];
    __half* Xs  = (__half*)(smem + SM_XS);
    __half* Ws  = (__half*)(smem + SM_WS);
    float*  ss  = (float*)(smem + SM_SS);
    float*  sq  = (float*)(smem + SM_SQ);
    float*  bsm = (float*)(smem + SM_BIAS);

    const int tid  = threadIdx.x;
    const int wid  = tid >> 5;
    const int lane = tid & 31;
    const int m0   = blockIdx.x * 128;

    if (tid < 32) ((float4*)bsm)[tid] = ((const float4*)bias)[tid];

    {
        const __half2* __restrict__ Wh2 = (const __half2*)g_Wh;
#pragma unroll
        for (int i = 0; i < 32; i++) {
            int idx = tid + i * 256;
            int n = idx >> 6, k2 = idx & 63;
            *(__half2*)&Ws[n * LDH + k2 * 2] = Wh2[idx];
        }
    }
    {
        const float4* __restrict__ X4 = (const float4*)X;
#pragma unroll
        for (int i = 0; i < 16; i++) {
            int idx = tid + i * 256;
            int row = idx >> 5, c4 = idx & 31;
            int gr = m0 + row;
            float4 v = make_float4(0.f, 0.f, 0.f, 0.f);
            if (gr < NVERT) v = X4[(size_t)gr * 32 + c4];
            __half2 p0 = __floats2half2_rn(v.x, v.y);
            __half2 p1 = __floats2half2_rn(v.z, v.w);
            uint2 pk;
            pk.x = *(uint32_t*)&p0; pk.y = *(uint32_t*)&p1;
            *(uint2*)&Xs[row * LDH + c4 * 4] = pk;
        }
    }
    __syncthreads();

    const int g   = lane >> 2;
    const int tig = lane & 3;

    float d[16][4];
#pragma unroll
    for (int t = 0; t < 16; t++)
#pragma unroll
        for (int j = 0; j < 4; j++) d[t][j] = 0.f;

    const __half* Xw = Xs + (wid * 16) * LDH;
#pragma unroll
    for (int kk = 0; kk < 8; kk++) {
        const int kb = kk * 16 + tig * 2;
        uint32_t a0 = *(const uint32_t*)&Xw[g * LDH + kb];
        uint32_t a1 = *(const uint32_t*)&Xw[(g + 8) * LDH + kb];
        uint32_t a2 = *(const uint32_t*)&Xw[g * LDH + kb + 8];
        uint32_t a3 = *(const uint32_t*)&Xw[(g + 8) * LDH + kb + 8];
#pragma unroll
        for (int t = 0; t < 16; t++) {
            uint32_t b0 = *(const uint32_t*)&Ws[(t * 8 + g) * LDH + kb];
            uint32_t b1 = *(const uint32_t*)&Ws[(t * 8 + g) * LDH + kb + 8];
            asm volatile(
                "mma.sync.aligned.m16n8k16.row.col.f32.f16.f16.f32 "
                "{%0,%1,%2,%3},{%4,%5,%6,%7},{%8,%9},{%0,%1,%2,%3};"
                : "+f"(d[t][0]), "+f"(d[t][1]), "+f"(d[t][2]), "+f"(d[t][3])
                : "r"(a0), "r"(a1), "r"(a2), "r"(a3), "r"(b0), "r"(b1));
        }
    }

    const int row0 = wid * 16 + g;
    const int gr0  = m0 + row0;
    const int gr1  = gr0 + 8;
    const bool ok0 = gr0 < NVERT;
    const bool ok1 = gr1 < NVERT;

#pragma unroll
    for (int t = 0; t < 16; t++) {
        const int c = t * 8 + tig * 2;
        float b0f = bsm[c], b1f = bsm[c + 1];
        float v0 = d[t][0] + b0f, v1 = d[t][1] + b1f;
        float v2 = d[t][2] + b0f, v3 = d[t][3] + b1f;
        if (ok0) *(__half2*)&g_h[(size_t)gr0 * HDIM + c] = __floats2half2_rn(v0, v1);
        if (ok1) *(__half2*)&g_h[(size_t)gr1 * HDIM + c] = __floats2half2_rn(v2, v3);

        float s0 = (ok0 ? v0 : 0.f) + (ok1 ? v2 : 0.f);
        float s1 = (ok0 ? v1 : 0.f) + (ok1 ? v3 : 0.f);
        float q0 = (ok0 ? v0 * v0 : 0.f) + (ok1 ? v2 * v2 : 0.f);
        float q1 = (ok0 ? v1 * v1 : 0.f) + (ok1 ? v3 * v3 : 0.f);
#pragma unroll
        for (int m = 4; m <= 16; m <<= 1) {
            s0 += __shfl_xor_sync(0xffffffffu, s0, m);
            s1 += __shfl_xor_sync(0xffffffffu, s1, m);
            q0 += __shfl_xor_sync(0xffffffffu, q0, m);
            q1 += __shfl_xor_sync(0xffffffffu, q1, m);
        }
        if (g == 0) {
            ss[wid * 128 + c] = s0; ss[wid * 128 + c + 1] = s1;
            sq[wid * 128 + c] = q0; sq[wid * 128 + c + 1] = q1;
        }
    }
    __syncthreads();

    if (tid < 128) {
        float t = 0.f;
#pragma unroll
        for (int r = 0; r < 8; r++) t += ss[r * 128 + tid];
        atomicAdd(&g_colsum[tid], t);
    } else {
        int c = tid - 128;
        float t = 0.f;
#pragma unroll
        for (int r = 0; r < 8; r++) t += sq[r * 128 + c];
        atomicAdd(&g_colsumsq[c], t);
    }
}

// ---------------- phase 1: edge means (finalize fused into prologue) ---------
__global__ void edge_agg_kernel(const float* __restrict__ gamma,
                                const float* __restrict__ beta) {
    __shared__ float s_scale[128], s_shift[128];
    const int tid  = threadIdx.x;
    // per-block BN finalize (replaces separate finalize_stats launch)
    if (tid < 128) {
        float mu  = g_colsum[tid] * (1.0f / NVERT);
        float var = g_colsumsq[tid] * (1.0f / NVERT) - mu * mu;
        float sc  = gamma[tid] * rsqrtf(var + BN_EPS);
        s_scale[tid] = sc;
        s_shift[tid] = beta[tid] - mu * sc;
    }
    __syncthreads();

    int w    = (blockIdx.x * blockDim.x + tid) >> 5;
    int lane = tid & 31;
    if (w >= NEDGE) return;

    int cnt = g_ecnt[w];
    int n   = min(cnt, ECAP);
    const int* __restrict__ bucket = &g_ebucket[(size_t)w * ECAP];
    const uint4* __restrict__ h4   = (const uint4*)g_h;

    const int half = lane >> 4;
    const int sub  = lane & 15;

    float a0 = 0.f, a1 = 0.f, a2 = 0.f, a3 = 0.f;
    float a4 = 0.f, a5 = 0.f, a6 = 0.f, a7 = 0.f;

    for (int j0 = 0; j0 < n; j0 += 32) {
        int my = (j0 + lane < n) ? bucket[j0 + lane] : 0;
        int nthis = min(32, n - j0);
#pragma unroll 2
        for (int t = 0; t < nthis; t += 2) {
            int idx = t + half;
            int v = __shfl_sync(0xffffffffu, my, idx);
            if (idx < nthis) {
                uint4 pk = __ldg(&h4[(size_t)v * 16 + sub]);
                float2 f0 = __half22float2(*(__half2*)&pk.x);
                float2 f1 = __half22float2(*(__half2*)&pk.y);
                float2 f2 = __half22float2(*(__half2*)&pk.z);
                float2 f3 = __half22float2(*(__half2*)&pk.w);
                a0 += f0.x; a1 += f0.y; a2 += f1.x; a3 += f1.y;
                a4 += f2.x; a5 += f2.y; a6 += f3.x; a7 += f3.y;
            }
        }
    }

    a0 += __shfl_down_sync(0xffffffffu, a0, 16);
    a1 += __shfl_down_sync(0xffffffffu, a1, 16);
    a2 += __shfl_down_sync(0xffffffffu, a2, 16);
    a3 += __shfl_down_sync(0xffffffffu, a3, 16);
    a4 += __shfl_down_sync(0xffffffffu, a4, 16);
    a5 += __shfl_down_sync(0xffffffffu, a5, 16);
    a6 += __shfl_down_sync(0xffffffffu, a6, 16);
    a7 += __shfl_down_sync(0xffffffffu, a7, 16);

    if (lane < 16) {
        uint4 opk; opk.x = opk.y = opk.z = opk.w = 0u;
        if (cnt > 0) {
            float inv = 1.0f / (float)cnt;
            float4 sc0 = ((const float4*)s_scale)[sub * 2];
            float4 sc1 = ((const float4*)s_scale)[sub * 2 + 1];
            float4 sh0 = ((const float4*)s_shift)[sub * 2];
            float4 sh1 = ((const float4*)s_shift)[sub * 2 + 1];
            __half2 p0 = __floats2half2_rn(fmaf(a0 * inv, sc0.x, sh0.x), fmaf(a1 * inv, sc0.y, sh0.y));
            __half2 p1 = __floats2half2_rn(fmaf(a2 * inv, sc0.z, sh0.z), fmaf(a3 * inv, sc0.w, sh0.w));
            __half2 p2 = __floats2half2_rn(fmaf(a4 * inv, sc1.x, sh1.x), fmaf(a5 * inv, sc1.y, sh1.y));
            __half2 p3 = __floats2half2_rn(fmaf(a6 * inv, sc1.z, sh1.z), fmaf(a7 * inv, sc1.w, sh1.w));
            opk.x = *(uint32_t*)&p0; opk.y = *(uint32_t*)&p1;
            opk.z = *(uint32_t*)&p2; opk.w = *(uint32_t*)&p3;
        }
        ((uint4*)g_Xe)[(size_t)w * 16 + sub] = opk;
    }
}

// ---------------- phase 2: vertex means + ReLU -------------------------------
__global__ void vert_agg_kernel(float* __restrict__ out) {
    int w    = (blockIdx.x * blockDim.x + threadIdx.x) >> 5;
    int lane = threadIdx.x & 31;
    if (w >= NVERT) return;

    int cnt = g_vcnt[w];
    int n   = min(cnt, VCAP);
    const int* __restrict__ bucket = &g_vbucket[(size_t)w * VCAP];
    const uint4* __restrict__ xe4  = (const uint4*)g_Xe;

    const int half = lane >> 4;
    const int sub  = lane & 15;

    float a0 = 0.f, a1 = 0.f, a2 = 0.f, a3 = 0.f;
    float a4 = 0.f, a5 = 0.f, a6 = 0.f, a7 = 0.f;

    for (int j0 = 0; j0 < n; j0 += 32) {
        int my = (j0 + lane < n) ? bucket[j0 + lane] : 0;
        int nthis = min(32, n - j0);
#pragma unroll 2
        for (int t = 0; t < nthis; t += 2) {
            int idx = t + half;
            int e = __shfl_sync(0xffffffffu, my, idx);
            if (idx < nthis) {
                uint4 pk = __ldg(&xe4[(size_t)e * 16 + sub]);
                float2 f0 = __half22float2(*(__half2*)&pk.x);
                float2 f1 = __half22float2(*(__half2*)&pk.y);
                float2 f2 = __half22float2(*(__half2*)&pk.z);
                float2 f3 = __half22float2(*(__half2*)&pk.w);
                a0 += f0.x; a1 += f0.y; a2 += f1.x; a3 += f1.y;
                a4 += f2.x; a5 += f2.y; a6 += f3.x; a7 += f3.y;
            }
        }
    }

    a0 += __shfl_down_sync(0xffffffffu, a0, 16);
    a1 += __shfl_down_sync(0xffffffffu, a1, 16);
    a2 += __shfl_down_sync(0xffffffffu, a2, 16);
    a3 += __shfl_down_sync(0xffffffffu, a3, 16);
    a4 += __shfl_down_sync(0xffffffffu, a4, 16);
    a5 += __shfl_down_sync(0xffffffffu, a5, 16);
    a6 += __shfl_down_sync(0xffffffffu, a6, 16);
    a7 += __shfl_down_sync(0xffffffffu, a7, 16);

    if (lane < 16) {
        float inv = (cnt > 0) ? 1.0f / (float)cnt : 0.0f;
        float4 o0, o1;
        o0.x = fmaxf(a0 * inv, 0.f); o0.y = fmaxf(a1 * inv, 0.f);
        o0.z = fmaxf(a2 * inv, 0.f); o0.w = fmaxf(a3 * inv, 0.f);
        o1.x = fmaxf(a4 * inv, 0.f); o1.y = fmaxf(a5 * inv, 0.f);
        o1.z = fmaxf(a6 * inv, 0.f); o1.w = fmaxf(a7 * inv, 0.f);
        ((float4*)out)[(size_t)w * 32 + sub * 2]     = o0;
        ((float4*)out)[(size_t)w * 32 + sub * 2 + 1] = o1;
    }
}

// ---------------- launcher: fork bucket-build onto side stream ---------------
extern "C" void kernel_launch(void* const* d_in, const int* in_sizes, int n_in,
                              void* d_out, int out_size) {
    const float* X     = (const float*)d_in[0];
    const int*   vid   = (const int*)d_in[1];
    const int*   eid   = (const int*)d_in[2];
    const float* W     = (const float*)d_in[3];
    const float* bias  = (const float*)d_in[4];
    const float* gamma = (const float*)d_in[5];
    const float* beta  = (const float*)d_in[6];
    float*       out   = (float*)d_out;

    static cudaStream_t sB = nullptr;
    static cudaEvent_t evFork = nullptr, evJoin = nullptr;
    if (sB == nullptr) {
        cudaStreamCreateWithFlags(&sB, cudaStreamNonBlocking);
        cudaEventCreateWithFlags(&evFork, cudaEventDisableTiming);
        cudaEventCreateWithFlags(&evJoin, cudaEventDisableTiming);
        cudaFuncSetAttribute(gemm_mma_kernel, cudaFuncAttributeMaxDynamicSharedMemorySize, SM_TOTAL);
    }

    void *p_ecnt, *p_vcnt;
    cudaGetSymbolAddress(&p_ecnt, g_ecnt);
    cudaGetSymbolAddress(&p_vcnt, g_vcnt);

    // fork side stream for the bucket build
    cudaEventRecord(evFork, 0);
    cudaStreamWaitEvent(sB, evFork, 0);
    cudaMemsetAsync(p_ecnt, 0, NEDGE * sizeof(int), sB);
    cudaMemsetAsync(p_vcnt, 0, NVERT * sizeof(int), sB);
    fill_kernel<<<(NPAIR / 4 + 255) / 256, 256, 0, sB>>>(vid, eid);
    cudaEventRecord(evJoin, sB);

    // main stream: prep (W fp16 + stats zero) -> GEMM (fused stats)
    prep_kernel<<<64, 256>>>(W);
    gemm_mma_kernel<<<(NVERT + 127) / 128, 256, SM_TOTAL>>>(X, bias);

    // join, then aggregation phases (edge_agg finalizes BN per-block)
    cudaStreamWaitEvent(0, evJoin, 0);
    edge_agg_kernel<<<(NEDGE * 32 + 255) / 256, 256>>>(gamma, beta);
    vert_agg_kernel<<<(NVERT * 32 + 255) / 256, 256>>>(out);
}

// round 7
// speedup vs baseline: 1.7829x; 1.0296x over previous
#include <cuda_runtime.h>
#include <cuda_fp16.h>
#include <stdint.h>

#define NVERT 100000
#define NEDGE 20000
#define NPAIR 1600000
#define FD 128
#define HDIM 128
#define ECAP 192
#define VCAP 64
#define BN_EPS 1e-5f

// ---------------- scratch ----------------------------------------------------
__device__ __align__(16) __half g_h[(size_t)NVERT * HDIM];     // 25.6 MB (fp16)
__device__ __align__(16) __half g_Xe[(size_t)NEDGE * HDIM];    // 5.1 MB (fp16)
__device__ __align__(16) __half g_Wh[FD * HDIM];               // W^T in fp16 [n][k]
__device__ int   g_ecnt[NEDGE];
__device__ int   g_vcnt[NVERT];
__device__ int   g_ebucket[(size_t)NEDGE * ECAP];
__device__ int   g_vbucket[(size_t)NVERT * VCAP];
__device__ float g_colsum[HDIM];
__device__ float g_colsumsq[HDIM];

// ---------------- prep: W transpose->fp16 + zero stats -----------------------
__global__ void prep_kernel(const float* __restrict__ W) {
    int idx = blockIdx.x * 256 + threadIdx.x;
    int k = idx >> 7, n = idx & 127;
    g_Wh[n * FD + k] = __float2half(W[idx]);
    if (blockIdx.x == 0 && threadIdx.x < 128) {
        g_colsum[threadIdx.x]   = 0.f;
        g_colsumsq[threadIdx.x] = 0.f;
    }
}

// ---------------- bucket build (4 pairs per thread) --------------------------
__global__ void fill_kernel(const int* __restrict__ vid, const int* __restrict__ eid) {
    int i = blockIdx.x * blockDim.x + threadIdx.x;
    if (i >= NPAIR / 4) return;
    int4 v4 = ((const int4*)vid)[i];
    int4 e4 = ((const int4*)eid)[i];
    int vv[4] = {v4.x, v4.y, v4.z, v4.w};
    int ee[4] = {e4.x, e4.y, e4.z, e4.w};
#pragma unroll
    for (int t = 0; t < 4; t++) {
        int a = atomicAdd(&g_ecnt[ee[t]], 1);
        if (a < ECAP) g_ebucket[(size_t)ee[t] * ECAP + a] = vv[t];
        int c = atomicAdd(&g_vcnt[vv[t]], 1);
        if (c < VCAP) g_vbucket[(size_t)vv[t] * VCAP + c] = ee[t];
    }
}

// ---------------- fp16 HMMA GEMM + bias + fp16 store + fused stats -----------
#define LDH 136
#define SM_XS   0
#define SM_WS   34816
#define SM_SS   69632
#define SM_SQ   73728
#define SM_BIAS 77824
#define SM_TOTAL 78336

__global__ void __launch_bounds__(256, 2) gemm_mma_kernel(const float* __restrict__ X,
                                                          const float* __restrict__ bias) {
    extern __shared__ char smem[];
    __half* Xs  = (__half*)(smem + SM_XS);
    __half* Ws  = (__half*)(smem + SM_WS);
    float*  ss  = (float*)(smem + SM_SS);
    float*  sq  = (float*)(smem + SM_SQ);
    float*  bsm = (float*)(smem + SM_BIAS);

    const int tid  = threadIdx.x;
    const int wid  = tid >> 5;
    const int lane = tid & 31;
    const int m0   = blockIdx.x * 128;

    if (tid < 32) ((float4*)bsm)[tid] = ((const float4*)bias)[tid];

    {
        const __half2* __restrict__ Wh2 = (const __half2*)g_Wh;
#pragma unroll
        for (int i = 0; i < 32; i++) {
            int idx = tid + i * 256;
            int n = idx >> 6, k2 = idx & 63;
            *(__half2*)&Ws[n * LDH + k2 * 2] = Wh2[idx];
        }
    }
    {
        const float4* __restrict__ X4 = (const float4*)X;
#pragma unroll
        for (int i = 0; i < 16; i++) {
            int idx = tid + i * 256;
            int row = idx >> 5, c4 = idx & 31;
            int gr = m0 + row;
            float4 v = make_float4(0.f, 0.f, 0.f, 0.f);
            if (gr < NVERT) v = X4[(size_t)gr * 32 + c4];
            __half2 p0 = __floats2half2_rn(v.x, v.y);
            __half2 p1 = __floats2half2_rn(v.z, v.w);
            uint2 pk;
            pk.x = *(uint32_t*)&p0; pk.y = *(uint32_t*)&p1;
            *(uint2*)&Xs[row * LDH + c4 * 4] = pk;
        }
    }
    __syncthreads();

    const int g   = lane >> 2;
    const int tig = lane & 3;

    float d[16][4];
#pragma unroll
    for (int t = 0; t < 16; t++)
#pragma unroll
        for (int j = 0; j < 4; j++) d[t][j] = 0.f;

    const __half* Xw = Xs + (wid * 16) * LDH;
#pragma unroll
    for (int kk = 0; kk < 8; kk++) {
        const int kb = kk * 16 + tig * 2;
        uint32_t a0 = *(const uint32_t*)&Xw[g * LDH + kb];
        uint32_t a1 = *(const uint32_t*)&Xw[(g + 8) * LDH + kb];
        uint32_t a2 = *(const uint32_t*)&Xw[g * LDH + kb + 8];
        uint32_t a3 = *(const uint32_t*)&Xw[(g + 8) * LDH + kb + 8];
#pragma unroll
        for (int t = 0; t < 16; t++) {
            uint32_t b0 = *(const uint32_t*)&Ws[(t * 8 + g) * LDH + kb];
            uint32_t b1 = *(const uint32_t*)&Ws[(t * 8 + g) * LDH + kb + 8];
            asm volatile(
                "mma.sync.aligned.m16n8k16.row.col.f32.f16.f16.f32 "
                "{%0,%1,%2,%3},{%4,%5,%6,%7},{%8,%9},{%0,%1,%2,%3};"
                : "+f"(d[t][0]), "+f"(d[t][1]), "+f"(d[t][2]), "+f"(d[t][3])
                : "r"(a0), "r"(a1), "r"(a2), "r"(a3), "r"(b0), "r"(b1));
        }
    }

    const int row0 = wid * 16 + g;
    const int gr0  = m0 + row0;
    const int gr1  = gr0 + 8;
    const bool ok0 = gr0 < NVERT;
    const bool ok1 = gr1 < NVERT;

#pragma unroll
    for (int t = 0; t < 16; t++) {
        const int c = t * 8 + tig * 2;
        float b0f = bsm[c], b1f = bsm[c + 1];
        float v0 = d[t][0] + b0f, v1 = d[t][1] + b1f;
        float v2 = d[t][2] + b0f, v3 = d[t][3] + b1f;
        if (ok0) *(__half2*)&g_h[(size_t)gr0 * HDIM + c] = __floats2half2_rn(v0, v1);
        if (ok1) *(__half2*)&g_h[(size_t)gr1 * HDIM + c] = __floats2half2_rn(v2, v3);

        float s0 = (ok0 ? v0 : 0.f) + (ok1 ? v2 : 0.f);
        float s1 = (ok0 ? v1 : 0.f) + (ok1 ? v3 : 0.f);
        float q0 = (ok0 ? v0 * v0 : 0.f) + (ok1 ? v2 * v2 : 0.f);
        float q1 = (ok0 ? v1 * v1 : 0.f) + (ok1 ? v3 * v3 : 0.f);
#pragma unroll
        for (int m = 4; m <= 16; m <<= 1) {
            s0 += __shfl_xor_sync(0xffffffffu, s0, m);
            s1 += __shfl_xor_sync(0xffffffffu, s1, m);
            q0 += __shfl_xor_sync(0xffffffffu, q0, m);
            q1 += __shfl_xor_sync(0xffffffffu, q1, m);
        }
        if (g == 0) {
            ss[wid * 128 + c] = s0; ss[wid * 128 + c + 1] = s1;
            sq[wid * 128 + c] = q0; sq[wid * 128 + c + 1] = q1;
        }
    }
    __syncthreads();

    if (tid < 128) {
        float t = 0.f;
#pragma unroll
        for (int r = 0; r < 8; r++) t += ss[r * 128 + tid];
        atomicAdd(&g_colsum[tid], t);
    } else {
        int c = tid - 128;
        float t = 0.f;
#pragma unroll
        for (int r = 0; r < 8; r++) t += sq[r * 128 + c];
        atomicAdd(&g_colsumsq[c], t);
    }
}

// ------ batched gather accumulate: 4 independent LDG.128 in flight -----------
// acc[8] accumulates 8 fp32 columns (sub*8 .. sub*8+7)
#define ACC_PK(pk) do { \
    float2 f0 = __half22float2(*(__half2*)&(pk).x); \
    float2 f1 = __half22float2(*(__half2*)&(pk).y); \
    float2 f2 = __half22float2(*(__half2*)&(pk).z); \
    float2 f3 = __half22float2(*(__half2*)&(pk).w); \
    acc[0] += f0.x; acc[1] += f0.y; acc[2] += f1.x; acc[3] += f1.y; \
    acc[4] += f2.x; acc[5] += f2.y; acc[6] += f3.x; acc[7] += f3.y; \
} while (0)

__device__ __forceinline__ void gather_rows(const uint4* __restrict__ base, int rowstride16,
                                            const int* __restrict__ bucket, int n,
                                            int lane, int half, int sub, float* acc) {
    for (int j0 = 0; j0 < n; j0 += 32) {
        int my = (j0 + lane < n) ? bucket[j0 + lane] : 0;
        int nthis = min(32, n - j0);
        for (int t = 0; t < nthis; t += 8) {
            int i0 = t + half, i1 = t + 2 + half, i2 = t + 4 + half, i3 = t + 6 + half;
            // invalid slots broadcast index 0 -> safe address; accumulate predicated
            int v0 = __shfl_sync(0xffffffffu, my, i0);
            int v1 = __shfl_sync(0xffffffffu, my, i1);
            int v2 = __shfl_sync(0xffffffffu, my, i2);
            int v3 = __shfl_sync(0xffffffffu, my, i3);
            uint4 p0 = __ldg(&base[(size_t)v0 * rowstride16 + sub]);
            uint4 p1 = __ldg(&base[(size_t)v1 * rowstride16 + sub]);
            uint4 p2 = __ldg(&base[(size_t)v2 * rowstride16 + sub]);
            uint4 p3 = __ldg(&base[(size_t)v3 * rowstride16 + sub]);
            if (i0 < nthis) ACC_PK(p0);
            if (i1 < nthis) ACC_PK(p1);
            if (i2 < nthis) ACC_PK(p2);
            if (i3 < nthis) ACC_PK(p3);
        }
    }
    // fold odd-half partials into even half
#pragma unroll
    for (int u = 0; u < 8; u++)
        acc[u] += __shfl_down_sync(0xffffffffu, acc[u], 16);
}

// ---------------- phase 1: edge means (BN finalize fused) --------------------
__global__ void edge_agg_kernel(const float* __restrict__ gamma,
                                const float* __restrict__ beta) {
    __shared__ float s_scale[128], s_shift[128];
    const int tid = threadIdx.x;
    if (tid < 128) {
        float mu  = g_colsum[tid] * (1.0f / NVERT);
        float var = g_colsumsq[tid] * (1.0f / NVERT) - mu * mu;
        float sc  = gamma[tid] * rsqrtf(var + BN_EPS);
        s_scale[tid] = sc;
        s_shift[tid] = beta[tid] - mu * sc;
    }
    __syncthreads();

    int w    = (blockIdx.x * blockDim.x + tid) >> 5;
    int lane = tid & 31;
    if (w >= NEDGE) return;

    int cnt = g_ecnt[w];
    int n   = min(cnt, ECAP);
    const int half = lane >> 4;
    const int sub  = lane & 15;

    float acc[8] = {0.f, 0.f, 0.f, 0.f, 0.f, 0.f, 0.f, 0.f};
    gather_rows((const uint4*)g_h, 16, &g_ebucket[(size_t)w * ECAP], n, lane, half, sub, acc);

    if (lane < 16) {
        uint4 opk; opk.x = opk.y = opk.z = opk.w = 0u;
        if (cnt > 0) {
            float inv = 1.0f / (float)cnt;
            float4 sc0 = ((const float4*)s_scale)[sub * 2];
            float4 sc1 = ((const float4*)s_scale)[sub * 2 + 1];
            float4 sh0 = ((const float4*)s_shift)[sub * 2];
            float4 sh1 = ((const float4*)s_shift)[sub * 2 + 1];
            __half2 p0 = __floats2half2_rn(fmaf(acc[0] * inv, sc0.x, sh0.x), fmaf(acc[1] * inv, sc0.y, sh0.y));
            __half2 p1 = __floats2half2_rn(fmaf(acc[2] * inv, sc0.z, sh0.z), fmaf(acc[3] * inv, sc0.w, sh0.w));
            __half2 p2 = __floats2half2_rn(fmaf(acc[4] * inv, sc1.x, sh1.x), fmaf(acc[5] * inv, sc1.y, sh1.y));
            __half2 p3 = __floats2half2_rn(fmaf(acc[6] * inv, sc1.z, sh1.z), fmaf(acc[7] * inv, sc1.w, sh1.w));
            opk.x = *(uint32_t*)&p0; opk.y = *(uint32_t*)&p1;
            opk.z = *(uint32_t*)&p2; opk.w = *(uint32_t*)&p3;
        }
        ((uint4*)g_Xe)[(size_t)w * 16 + sub] = opk;
    }
}

// ---------------- phase 2: vertex means + ReLU -------------------------------
__global__ void vert_agg_kernel(float* __restrict__ out) {
    int w    = (blockIdx.x * blockDim.x + threadIdx.x) >> 5;
    int lane = threadIdx.x & 31;
    if (w >= NVERT) return;

    int cnt = g_vcnt[w];
    int n   = min(cnt, VCAP);
    const int half = lane >> 4;
    const int sub  = lane & 15;

    float acc[8] = {0.f, 0.f, 0.f, 0.f, 0.f, 0.f, 0.f, 0.f};
    gather_rows((const uint4*)g_Xe, 16, &g_vbucket[(size_t)w * VCAP], n, lane, half, sub, acc);

    if (lane < 16) {
        float inv = (cnt > 0) ? 1.0f / (float)cnt : 0.0f;
        float4 o0, o1;
        o0.x = fmaxf(acc[0] * inv, 0.f); o0.y = fmaxf(acc[1] * inv, 0.f);
        o0.z = fmaxf(acc[2] * inv, 0.f); o0.w = fmaxf(acc[3] * inv, 0.f);
        o1.x = fmaxf(acc[4] * inv, 0.f); o1.y = fmaxf(acc[5] * inv, 0.f);
        o1.z = fmaxf(acc[6] * inv, 0.f); o1.w = fmaxf(acc[7] * inv, 0.f);
        ((float4*)out)[(size_t)w * 32 + sub * 2]     = o0;
        ((float4*)out)[(size_t)w * 32 + sub * 2 + 1] = o1;
    }
}

// ---------------- launcher ----------------------------------------------------
extern "C" void kernel_launch(void* const* d_in, const int* in_sizes, int n_in,
                              void* d_out, int out_size) {
    const float* X     = (const float*)d_in[0];
    const int*   vid   = (const int*)d_in[1];
    const int*   eid   = (const int*)d_in[2];
    const float* W     = (const float*)d_in[3];
    const float* bias  = (const float*)d_in[4];
    const float* gamma = (const float*)d_in[5];
    const float* beta  = (const float*)d_in[6];
    float*       out   = (float*)d_out;

    static cudaStream_t sB = nullptr;
    static cudaEvent_t evFork = nullptr, evJoin = nullptr;
    if (sB == nullptr) {
        cudaStreamCreateWithFlags(&sB, cudaStreamNonBlocking);
        cudaEventCreateWithFlags(&evFork, cudaEventDisableTiming);
        cudaEventCreateWithFlags(&evJoin, cudaEventDisableTiming);
        cudaFuncSetAttribute(gemm_mma_kernel, cudaFuncAttributeMaxDynamicSharedMemorySize, SM_TOTAL);
    }

    void *p_ecnt, *p_vcnt;
    cudaGetSymbolAddress(&p_ecnt, g_ecnt);
    cudaGetSymbolAddress(&p_vcnt, g_vcnt);

    cudaEventRecord(evFork, 0);
    cudaStreamWaitEvent(sB, evFork, 0);
    cudaMemsetAsync(p_ecnt, 0, NEDGE * sizeof(int), sB);
    cudaMemsetAsync(p_vcnt, 0, NVERT * sizeof(int), sB);
    fill_kernel<<<(NPAIR / 4 + 255) / 256, 256, 0, sB>>>(vid, eid);
    cudaEventRecord(evJoin, sB);

    prep_kernel<<<64, 256>>>(W);
    gemm_mma_kernel<<<(NVERT + 127) / 128, 256, SM_TOTAL>>>(X, bias);

    cudaStreamWaitEvent(0, evJoin, 0);
    edge_agg_kernel<<<(NEDGE * 32 + 255) / 256, 256>>>(gamma, beta);
    vert_agg_kernel<<<(NVERT * 32 + 255) / 256, 256>>>(out);
}

// round 8
// speedup vs baseline: 1.8540x; 1.0399x over previous
#include <cuda_runtime.h>
#include <cuda_fp16.h>
#include <stdint.h>

#define NVERT 100000
#define NEDGE 20000
#define NPAIR 1600000
#define FD 128
#define HDIM 128
#define ECAP 192
#define VCAP 64
#define BN_EPS 1e-5f

// ---------------- scratch ----------------------------------------------------
__device__ __align__(16) __half g_h[(size_t)NVERT * HDIM];     // 25.6 MB (fp16)
__device__ __align__(16) __half g_Xe[(size_t)NEDGE * HDIM];    // 5.1 MB (fp16)
__device__ __align__(16) __half g_Wh[FD * HDIM];               // W^T in fp16 [n][k]
__device__ int   g_ecnt[NEDGE];
__device__ int   g_vcnt[NVERT];
__device__ int   g_ebucket[(size_t)NEDGE * ECAP];
__device__ int   g_vbucket[(size_t)NVERT * VCAP];
__device__ float g_colsum[HDIM];
__device__ float g_colsumsq[HDIM];

// ---------------- prep: W transpose->fp16 + zero stats -----------------------
__global__ void prep_kernel(const float* __restrict__ W) {
    int idx = blockIdx.x * 256 + threadIdx.x;
    int k = idx >> 7, n = idx & 127;
    g_Wh[n * FD + k] = __float2half(W[idx]);
    if (blockIdx.x == 0 && threadIdx.x < 128) {
        g_colsum[threadIdx.x]   = 0.f;
        g_colsumsq[threadIdx.x] = 0.f;
    }
}

// ---------------- bucket build (4 pairs per thread) --------------------------
__global__ void fill_kernel(const int* __restrict__ vid, const int* __restrict__ eid) {
    int i = blockIdx.x * blockDim.x + threadIdx.x;
    if (i >= NPAIR / 4) return;
    int4 v4 = ((const int4*)vid)[i];
    int4 e4 = ((const int4*)eid)[i];
    int vv[4] = {v4.x, v4.y, v4.z, v4.w};
    int ee[4] = {e4.x, e4.y, e4.z, e4.w};
#pragma unroll
    for (int t = 0; t < 4; t++) {
        int a = atomicAdd(&g_ecnt[ee[t]], 1);
        if (a < ECAP) g_ebucket[(size_t)ee[t] * ECAP + a] = vv[t];
        int c = atomicAdd(&g_vcnt[vv[t]], 1);
        if (c < VCAP) g_vbucket[(size_t)vv[t] * VCAP + c] = ee[t];
    }
}

// ---------------- fp16 HMMA GEMM (64x128 tile) + fused stats -----------------
// 256 threads = 8 warps: warp = (rowgroup rg 0..3) x (n-half nh 0..1)
// each warp: rows rg*16..+16, cols nh*64..+64  -> d[8][4]
#define LDH 136
#define SM_XS   0                      // 64*136*2   = 17408
#define SM_WS   17408                  // 128*136*2  = 34816
#define SM_SS   52224                  // 4*128*4    = 2048
#define SM_SQ   54272                  // 2048
#define SM_BIAS 56320                  // 512
#define SM_TOTAL 56832

__global__ void __launch_bounds__(256, 3) gemm_mma_kernel(const float* __restrict__ X,
                                                          const float* __restrict__ bias) {
    extern __shared__ char smem[];
    __half* Xs  = (__half*)(smem + SM_XS);
    __half* Ws  = (__half*)(smem + SM_WS);
    float*  ss  = (float*)(smem + SM_SS);
    float*  sq  = (float*)(smem + SM_SQ);
    float*  bsm = (float*)(smem + SM_BIAS);

    const int tid  = threadIdx.x;
    const int wid  = tid >> 5;
    const int lane = tid & 31;
    const int rg   = wid >> 1;        // row group 0..3
    const int nh   = wid & 1;         // n half 0..1
    const int m0   = blockIdx.x * 64;

    if (tid < 32) ((float4*)bsm)[tid] = ((const float4*)bias)[tid];

    // W fp16 [n][k] -> smem (full 128x128)
    {
        const __half2* __restrict__ Wh2 = (const __half2*)g_Wh;
#pragma unroll
        for (int i = 0; i < 32; i++) {
            int idx = tid + i * 256;
            int n = idx >> 6, k2 = idx & 63;
            *(__half2*)&Ws[n * LDH + k2 * 2] = Wh2[idx];
        }
    }
    // X tile (64 rows) fp32 -> fp16 smem
    {
        const float4* __restrict__ X4 = (const float4*)X;
#pragma unroll
        for (int i = 0; i < 8; i++) {
            int idx = tid + i * 256;          // 2048 float4
            int row = idx >> 5, c4 = idx & 31;
            int gr = m0 + row;
            float4 v = make_float4(0.f, 0.f, 0.f, 0.f);
            if (gr < NVERT) v = X4[(size_t)gr * 32 + c4];
            __half2 p0 = __floats2half2_rn(v.x, v.y);
            __half2 p1 = __floats2half2_rn(v.z, v.w);
            uint2 pk;
            pk.x = *(uint32_t*)&p0; pk.y = *(uint32_t*)&p1;
            *(uint2*)&Xs[row * LDH + c4 * 4] = pk;
        }
    }
    __syncthreads();

    const int g   = lane >> 2;
    const int tig = lane & 3;

    float d[8][4];
#pragma unroll
    for (int t = 0; t < 8; t++)
#pragma unroll
        for (int j = 0; j < 4; j++) d[t][j] = 0.f;

    const __half* Xw = Xs + (rg * 16) * LDH;
    const __half* Wn = Ws + (nh * 64) * LDH;
#pragma unroll
    for (int kk = 0; kk < 8; kk++) {
        const int kb = kk * 16 + tig * 2;
        uint32_t a0 = *(const uint32_t*)&Xw[g * LDH + kb];
        uint32_t a1 = *(const uint32_t*)&Xw[(g + 8) * LDH + kb];
        uint32_t a2 = *(const uint32_t*)&Xw[g * LDH + kb + 8];
        uint32_t a3 = *(const uint32_t*)&Xw[(g + 8) * LDH + kb + 8];
#pragma unroll
        for (int t = 0; t < 8; t++) {
            uint32_t b0 = *(const uint32_t*)&Wn[(t * 8 + g) * LDH + kb];
            uint32_t b1 = *(const uint32_t*)&Wn[(t * 8 + g) * LDH + kb + 8];
            asm volatile(
                "mma.sync.aligned.m16n8k16.row.col.f32.f16.f16.f32 "
                "{%0,%1,%2,%3},{%4,%5,%6,%7},{%8,%9},{%0,%1,%2,%3};"
                : "+f"(d[t][0]), "+f"(d[t][1]), "+f"(d[t][2]), "+f"(d[t][3])
                : "r"(a0), "r"(a1), "r"(a2), "r"(a3), "r"(b0), "r"(b1));
        }
    }

    const int gr0 = m0 + rg * 16 + g;
    const int gr1 = gr0 + 8;
    const bool ok0 = gr0 < NVERT;
    const bool ok1 = gr1 < NVERT;

#pragma unroll
    for (int t = 0; t < 8; t++) {
        const int c = nh * 64 + t * 8 + tig * 2;
        float b0f = bsm[c], b1f = bsm[c + 1];
        float v0 = d[t][0] + b0f, v1 = d[t][1] + b1f;
        float v2 = d[t][2] + b0f, v3 = d[t][3] + b1f;
        if (ok0) *(__half2*)&g_h[(size_t)gr0 * HDIM + c] = __floats2half2_rn(v0, v1);
        if (ok1) *(__half2*)&g_h[(size_t)gr1 * HDIM + c] = __floats2half2_rn(v2, v3);

        float s0 = (ok0 ? v0 : 0.f) + (ok1 ? v2 : 0.f);
        float s1 = (ok0 ? v1 : 0.f) + (ok1 ? v3 : 0.f);
        float q0 = (ok0 ? v0 * v0 : 0.f) + (ok1 ? v2 * v2 : 0.f);
        float q1 = (ok0 ? v1 * v1 : 0.f) + (ok1 ? v3 * v3 : 0.f);
#pragma unroll
        for (int m = 4; m <= 16; m <<= 1) {
            s0 += __shfl_xor_sync(0xffffffffu, s0, m);
            s1 += __shfl_xor_sync(0xffffffffu, s1, m);
            q0 += __shfl_xor_sync(0xffffffffu, q0, m);
            q1 += __shfl_xor_sync(0xffffffffu, q1, m);
        }
        if (g == 0) {   // lanes 0..3 hold the 16-row column sums
            ss[rg * 128 + c] = s0; ss[rg * 128 + c + 1] = s1;
            sq[rg * 128 + c] = q0; sq[rg * 128 + c + 1] = q1;
        }
    }
    __syncthreads();

    if (tid < 128) {
        float t = ss[tid] + ss[128 + tid] + ss[256 + tid] + ss[384 + tid];
        atomicAdd(&g_colsum[tid], t);
    } else {
        int c = tid - 128;
        float t = sq[c] + sq[128 + c] + sq[256 + c] + sq[384 + c];
        atomicAdd(&g_colsumsq[c], t);
    }
}

// ------ batched gather accumulate: 4 independent LDG.128 in flight -----------
#define ACC_PK(pk) do { \
    float2 f0 = __half22float2(*(__half2*)&(pk).x); \
    float2 f1 = __half22float2(*(__half2*)&(pk).y); \
    float2 f2 = __half22float2(*(__half2*)&(pk).z); \
    float2 f3 = __half22float2(*(__half2*)&(pk).w); \
    acc[0] += f0.x; acc[1] += f0.y; acc[2] += f1.x; acc[3] += f1.y; \
    acc[4] += f2.x; acc[5] += f2.y; acc[6] += f3.x; acc[7] += f3.y; \
} while (0)

__device__ __forceinline__ void gather_rows(const uint4* __restrict__ base, int rowstride16,
                                            const int* __restrict__ bucket, int n,
                                            int lane, int half, int sub, float* acc) {
    for (int j0 = 0; j0 < n; j0 += 32) {
        int my = (j0 + lane < n) ? bucket[j0 + lane] : 0;
        int nthis = min(32, n - j0);
        for (int t = 0; t < nthis; t += 8) {
            int i0 = t + half, i1 = t + 2 + half, i2 = t + 4 + half, i3 = t + 6 + half;
            int v0 = __shfl_sync(0xffffffffu, my, i0);
            int v1 = __shfl_sync(0xffffffffu, my, i1);
            int v2 = __shfl_sync(0xffffffffu, my, i2);
            int v3 = __shfl_sync(0xffffffffu, my, i3);
            uint4 p0 = __ldg(&base[(size_t)v0 * rowstride16 + sub]);
            uint4 p1 = __ldg(&base[(size_t)v1 * rowstride16 + sub]);
            uint4 p2 = __ldg(&base[(size_t)v2 * rowstride16 + sub]);
            uint4 p3 = __ldg(&base[(size_t)v3 * rowstride16 + sub]);
            if (i0 < nthis) ACC_PK(p0);
            if (i1 < nthis) ACC_PK(p1);
            if (i2 < nthis) ACC_PK(p2);
            if (i3 < nthis) ACC_PK(p3);
        }
    }
#pragma unroll
    for (int u = 0; u < 8; u++)
        acc[u] += __shfl_down_sync(0xffffffffu, acc[u], 16);
}

// ---------------- phase 1: edge means (BN finalize fused) --------------------
__global__ void __launch_bounds__(256, 6) edge_agg_kernel(const float* __restrict__ gamma,
                                                          const float* __restrict__ beta) {
    __shared__ float s_scale[128], s_shift[128];
    const int tid = threadIdx.x;
    if (tid < 128) {
        float mu  = g_colsum[tid] * (1.0f / NVERT);
        float var = g_colsumsq[tid] * (1.0f / NVERT) - mu * mu;
        float sc  = gamma[tid] * rsqrtf(var + BN_EPS);
        s_scale[tid] = sc;
        s_shift[tid] = beta[tid] - mu * sc;
    }
    __syncthreads();

    int w    = (blockIdx.x * blockDim.x + tid) >> 5;
    int lane = tid & 31;
    if (w >= NEDGE) return;

    int cnt = g_ecnt[w];
    int n   = min(cnt, ECAP);
    const int half = lane >> 4;
    const int sub  = lane & 15;

    float acc[8] = {0.f, 0.f, 0.f, 0.f, 0.f, 0.f, 0.f, 0.f};
    gather_rows((const uint4*)g_h, 16, &g_ebucket[(size_t)w * ECAP], n, lane, half, sub, acc);

    if (lane < 16) {
        uint4 opk; opk.x = opk.y = opk.z = opk.w = 0u;
        if (cnt > 0) {
            float inv = 1.0f / (float)cnt;
            float4 sc0 = ((const float4*)s_scale)[sub * 2];
            float4 sc1 = ((const float4*)s_scale)[sub * 2 + 1];
            float4 sh0 = ((const float4*)s_shift)[sub * 2];
            float4 sh1 = ((const float4*)s_shift)[sub * 2 + 1];
            __half2 p0 = __floats2half2_rn(fmaf(acc[0] * inv, sc0.x, sh0.x), fmaf(acc[1] * inv, sc0.y, sh0.y));
            __half2 p1 = __floats2half2_rn(fmaf(acc[2] * inv, sc0.z, sh0.z), fmaf(acc[3] * inv, sc0.w, sh0.w));
            __half2 p2 = __floats2half2_rn(fmaf(acc[4] * inv, sc1.x, sh1.x), fmaf(acc[5] * inv, sc1.y, sh1.y));
            __half2 p3 = __floats2half2_rn(fmaf(acc[6] * inv, sc1.z, sh1.z), fmaf(acc[7] * inv, sc1.w, sh1.w));
            opk.x = *(uint32_t*)&p0; opk.y = *(uint32_t*)&p1;
            opk.z = *(uint32_t*)&p2; opk.w = *(uint32_t*)&p3;
        }
        ((uint4*)g_Xe)[(size_t)w * 16 + sub] = opk;
    }
}

// ---------------- phase 2: vertex means + ReLU -------------------------------
__global__ void __launch_bounds__(256, 6) vert_agg_kernel(float* __restrict__ out) {
    int w    = (blockIdx.x * blockDim.x + threadIdx.x) >> 5;
    int lane = threadIdx.x & 31;
    if (w >= NVERT) return;

    int cnt = g_vcnt[w];
    int n   = min(cnt, VCAP);
    const int half = lane >> 4;
    const int sub  = lane & 15;

    float acc[8] = {0.f, 0.f, 0.f, 0.f, 0.f, 0.f, 0.f, 0.f};
    gather_rows((const uint4*)g_Xe, 16, &g_vbucket[(size_t)w * VCAP], n, lane, half, sub, acc);

    if (lane < 16) {
        float inv = (cnt > 0) ? 1.0f / (float)cnt : 0.0f;
        float4 o0, o1;
        o0.x = fmaxf(acc[0] * inv, 0.f); o0.y = fmaxf(acc[1] * inv, 0.f);
        o0.z = fmaxf(acc[2] * inv, 0.f); o0.w = fmaxf(acc[3] * inv, 0.f);
        o1.x = fmaxf(acc[4] * inv, 0.f); o1.y = fmaxf(acc[5] * inv, 0.f);
        o1.z = fmaxf(acc[6] * inv, 0.f); o1.w = fmaxf(acc[7] * inv, 0.f);
        ((float4*)out)[(size_t)w * 32 + sub * 2]     = o0;
        ((float4*)out)[(size_t)w * 32 + sub * 2 + 1] = o1;
    }
}

// ---------------- launcher ----------------------------------------------------
extern "C" void kernel_launch(void* const* d_in, const int* in_sizes, int n_in,
                              void* d_out, int out_size) {
    const float* X     = (const float*)d_in[0];
    const int*   vid   = (const int*)d_in[1];
    const int*   eid   = (const int*)d_in[2];
    const float* W     = (const float*)d_in[3];
    const float* bias  = (const float*)d_in[4];
    const float* gamma = (const float*)d_in[5];
    const float* beta  = (const float*)d_in[6];
    float*       out   = (float*)d_out;

    static cudaStream_t sB = nullptr;
    static cudaEvent_t evFork = nullptr, evJoin = nullptr;
    if (sB == nullptr) {
        cudaStreamCreateWithFlags(&sB, cudaStreamNonBlocking);
        cudaEventCreateWithFlags(&evFork, cudaEventDisableTiming);
        cudaEventCreateWithFlags(&evJoin, cudaEventDisableTiming);
        cudaFuncSetAttribute(gemm_mma_kernel, cudaFuncAttributeMaxDynamicSharedMemorySize, SM_TOTAL);
    }

    void *p_ecnt, *p_vcnt;
    cudaGetSymbolAddress(&p_ecnt, g_ecnt);
    cudaGetSymbolAddress(&p_vcnt, g_vcnt);

    cudaEventRecord(evFork, 0);
    cudaStreamWaitEvent(sB, evFork, 0);
    cudaMemsetAsync(p_ecnt, 0, NEDGE * sizeof(int), sB);
    cudaMemsetAsync(p_vcnt, 0, NVERT * sizeof(int), sB);
    fill_kernel<<<(NPAIR / 4 + 255) / 256, 256, 0, sB>>>(vid, eid);
    cudaEventRecord(evJoin, sB);

    prep_kernel<<<64, 256>>>(W);
    gemm_mma_kernel<<<(NVERT + 63) / 64, 256, SM_TOTAL>>>(X, bias);

    cudaStreamWaitEvent(0, evJoin, 0);
    edge_agg_kernel<<<(NEDGE * 32 + 255) / 256, 256>>>(gamma, beta);
    vert_agg_kernel<<<(NVERT * 32 + 255) / 256, 256>>>(out);
}